// round 12
// baseline (speedup 1.0000x reference)
#include <cuda_runtime.h>
#include <math.h>

#define B_ 512
#define N_ 128
#define E_ 256
#define H_ 8
#define D_ 32
#define SCALE_ 0.17677669529663687f  /* 1/sqrt(32) */
#define NEGV  (-1000000000.0f)
#define CLIPV 10.0f
#define MTU   129                    /* Ms4T row stride in float4 units */
#define MRC   8                      /* M float4s cached in registers per thread */

typedef unsigned long long u64;

// packed fp32x2 FMA: d = a*b + d  (elementwise on (lo,hi))
__device__ __forceinline__ void ffma2(u64& d, u64 a, u64 b) {
    asm("fma.rn.f32x2 %0, %1, %2, %0;" : "+l"(d) : "l"(a), "l"(b));
}
__device__ __forceinline__ u64 pack2(float x, float y) {
    u64 r; asm("mov.b64 %0, {%1, %2};" : "=l"(r) : "f"(x), "f"(y)); return r;
}
__device__ __forceinline__ float2 unpack2(u64 v) {
    float2 r; asm("mov.b64 {%0, %1}, %2;" : "=f"(r.x), "=f"(r.y) : "l"(v)); return r;
}

// ---------------- scratch (device globals; no allocation) ----------------
__device__ float g_qkv[(size_t)B_ * N_ * 768];   // k | v | logit_k
__device__ float g_Qc [(size_t)B_ * N_ * E_];    // X @ Wstep_bot
__device__ float g_M  [(size_t)B_ * N_ * E_];    // logit_k @ Wmlp^T
__device__ float g_P  [(size_t)B_ * N_ * 1024];  // precomputed attn logits [b][i][h][n]
__device__ float g_vt [(size_t)B_ * E_ * N_];    // v transposed [b][d][n]
__device__ float g_bdot[B_ * N_];
__device__ float g_ge [B_ * E_];
__device__ float g_qf [B_ * E_];

// ---------------- graph_emb = mean over nodes ----------------
__global__ void mean_k(const float* __restrict__ ne) {
    int b = blockIdx.x, e = threadIdx.x;
    const float* p = ne + (size_t)b * N_ * E_ + e;
    float s = 0.f;
#pragma unroll 8
    for (int n = 0; n < N_; n++) s += p[(size_t)n * E_];
    g_ge[b * E_ + e] = s * (1.0f / N_);
}

// ---------------- q_first = ge@Wfix + first@Wstep_top + bfix + bstep ----------------
__global__ void qfirst_k(const float* __restrict__ ne,
                         const float* __restrict__ Wfix, const float* __restrict__ bfix,
                         const float* __restrict__ Wstep, const float* __restrict__ bstep) {
    __shared__ float ge_s[E_], fi_s[E_];
    int b = blockIdx.x, t = threadIdx.x;
    ge_s[t] = g_ge[b * E_ + t];
    fi_s[t] = ne[(size_t)b * N_ * E_ + t];
    __syncthreads();
    float acc = bfix[t] + bstep[t];
#pragma unroll 4
    for (int f = 0; f < E_; f++) {
        acc = fmaf(ge_s[f], Wfix[f * E_ + t], acc);
        acc = fmaf(fi_s[f], Wstep[f * E_ + t], acc);
    }
    g_qf[b * E_ + t] = acc;
}

// ---------------- generic fp32 GEMM, double-buffered pipeline ----------------
// C = A(MxK)*B(KxN) [+bias]; one __syncthreads per K-tile; FFMA2 core.
template <int TRANSB>
__global__ void __launch_bounds__(256, 2) sgemm_k(
    const float* __restrict__ A, const float* __restrict__ Bm,
    const float* __restrict__ bias, float* __restrict__ C,
    int K, int lda, int ldb, int ldc) {
    __shared__ __align__(16) float As[2][8][128];
    __shared__ __align__(16) float Bs[2][8][128];
    int tid = threadIdx.x;
    int tx = tid & 15, ty = tid >> 4;
    int rowBase = blockIdx.y * 128;
    int colBase = blockIdx.x * 128;

    u64 acc2[8][4];
#pragma unroll
    for (int i = 0; i < 8; i++)
#pragma unroll
        for (int j = 0; j < 4; j++) acc2[i][j] = 0ULL;

    int aR = tid >> 1;
    int aC = (tid & 1) * 4;
    int bK_n = tid >> 5;
    int bC_n = (tid & 31) * 4;
    int bCol_t = tid & 127;
    int bK_t = (tid >> 7) * 4;

    const float* Aptr = A + (size_t)(rowBase + aR) * lda + aC;
    const float* Bptr_n = Bm + (size_t)bK_n * ldb + colBase + bC_n;
    const float* Bptr_t = Bm + (size_t)(colBase + bCol_t) * ldb + bK_t;

    // prologue: tile 0 -> smem[0]
    float4 avr = *(const float4*)(Aptr);
    float4 bvr = TRANSB ? *(const float4*)(Bptr_t) : *(const float4*)(Bptr_n);
    {
        As[0][aC + 0][aR] = avr.x; As[0][aC + 1][aR] = avr.y;
        As[0][aC + 2][aR] = avr.z; As[0][aC + 3][aR] = avr.w;
        if (!TRANSB) {
            *(float4*)&Bs[0][bK_n][bC_n] = bvr;
        } else {
            Bs[0][bK_t + 0][bCol_t] = bvr.x; Bs[0][bK_t + 1][bCol_t] = bvr.y;
            Bs[0][bK_t + 2][bCol_t] = bvr.z; Bs[0][bK_t + 3][bCol_t] = bvr.w;
        }
    }
    __syncthreads();

    int buf = 0;
    for (int kt = 0; kt < K; kt += 8) {
        bool has_next = (kt + 8) < K;
        if (has_next) {
            avr = *(const float4*)(Aptr + kt + 8);
            bvr = TRANSB ? *(const float4*)(Bptr_t + kt + 8)
                         : *(const float4*)(Bptr_n + (size_t)(kt + 8) * ldb);
        }
        // compute on smem[buf]
#pragma unroll
        for (int kk = 0; kk < 8; kk++) {
            float ra[8];
            u64 rb2[4];
            *(float4*)&ra[0] = *(const float4*)&As[buf][kk][ty * 8];
            *(float4*)&ra[4] = *(const float4*)&As[buf][kk][ty * 8 + 4];
            {
                ulonglong2 t0 = *(const ulonglong2*)&Bs[buf][kk][tx * 8];
                ulonglong2 t1 = *(const ulonglong2*)&Bs[buf][kk][tx * 8 + 4];
                rb2[0] = t0.x; rb2[1] = t0.y; rb2[2] = t1.x; rb2[3] = t1.y;
            }
#pragma unroll
            for (int i = 0; i < 8; i++) {
                u64 raa = pack2(ra[i], ra[i]);
#pragma unroll
                for (int j = 0; j < 4; j++) ffma2(acc2[i][j], raa, rb2[j]);
            }
        }
        if (has_next) {
            int nb = buf ^ 1;
            As[nb][aC + 0][aR] = avr.x; As[nb][aC + 1][aR] = avr.y;
            As[nb][aC + 2][aR] = avr.z; As[nb][aC + 3][aR] = avr.w;
            if (!TRANSB) {
                *(float4*)&Bs[nb][bK_n][bC_n] = bvr;
            } else {
                Bs[nb][bK_t + 0][bCol_t] = bvr.x; Bs[nb][bK_t + 1][bCol_t] = bvr.y;
                Bs[nb][bK_t + 2][bCol_t] = bvr.z; Bs[nb][bK_t + 3][bCol_t] = bvr.w;
            }
            __syncthreads();
            buf = nb;
        }
    }
#pragma unroll
    for (int i = 0; i < 8; i++) {
        int r = rowBase + ty * 8 + i;
#pragma unroll
        for (int j = 0; j < 2; j++) {
            int c = colBase + tx * 8 + j * 4;
            float2 p0 = unpack2(acc2[i][2 * j + 0]);
            float2 p1 = unpack2(acc2[i][2 * j + 1]);
            float4 v;
            v.x = p0.x; v.y = p0.y; v.z = p1.x; v.w = p1.y;
            if (bias) { v.x += bias[c]; v.y += bias[c + 1]; v.z += bias[c + 2]; v.w += bias[c + 3]; }
            *(float4*)(C + (size_t)r * ldc + c) = v;
        }
    }
}

// ---------------- P[b][i][h][n] = SCALE * (qf[b]+Qc[b][i])_h . k[b][n]_h ----------------
__global__ void __launch_bounds__(256) pmat_k(float* __restrict__ P) {
    __shared__ __align__(16) float kt[32][132];
    __shared__ __align__(16) float qt[32][132];
    int h = blockIdx.x & 7, b = blockIdx.x >> 3;
    int tid = threadIdx.x;
    const float* kb  = g_qkv + (size_t)b * N_ * 768 + h * 32;
    const float* qcb = g_Qc  + (size_t)b * N_ * 256 + h * 32;
    const float* qfb = g_qf  + b * 256 + h * 32;

    for (int idx = tid; idx < N_ * 8; idx += 256) {
        int n = idx >> 3, d4 = (idx & 7) * 4;
        float4 kv  = *(const float4*)(kb  + (size_t)n * 768 + d4);
        float4 qv  = *(const float4*)(qcb + (size_t)n * 256 + d4);
        float4 qf4 = *(const float4*)(qfb + d4);
        kt[d4 + 0][n] = kv.x; kt[d4 + 1][n] = kv.y;
        kt[d4 + 2][n] = kv.z; kt[d4 + 3][n] = kv.w;
        qt[d4 + 0][n] = qv.x + qf4.x; qt[d4 + 1][n] = qv.y + qf4.y;
        qt[d4 + 2][n] = qv.z + qf4.z; qt[d4 + 3][n] = qv.w + qf4.w;
    }
    __syncthreads();

    int tx = tid & 15, ty = tid >> 4;
    u64 acc2[8][4];
#pragma unroll
    for (int i = 0; i < 8; i++)
#pragma unroll
        for (int j = 0; j < 4; j++) acc2[i][j] = 0ULL;

#pragma unroll 4
    for (int d = 0; d < 32; d++) {
        float ra[8];
        u64 rb2[4];
        *(float4*)&ra[0] = *(const float4*)&qt[d][ty * 8];
        *(float4*)&ra[4] = *(const float4*)&qt[d][ty * 8 + 4];
        {
            ulonglong2 t0 = *(const ulonglong2*)&kt[d][tx * 8];
            ulonglong2 t1 = *(const ulonglong2*)&kt[d][tx * 8 + 4];
            rb2[0] = t0.x; rb2[1] = t0.y; rb2[2] = t1.x; rb2[3] = t1.y;
        }
#pragma unroll
        for (int i = 0; i < 8; i++) {
            u64 raa = pack2(ra[i], ra[i]);
#pragma unroll
            for (int j = 0; j < 4; j++) ffma2(acc2[i][j], raa, rb2[j]);
        }
    }

#pragma unroll
    for (int i = 0; i < 8; i++) {
        float* row = P + ((size_t)(b * N_ + ty * 8 + i)) * 1024 + h * 128 + tx * 8;
#pragma unroll
        for (int j = 0; j < 2; j++) {
            float2 p0 = unpack2(acc2[i][2 * j + 0]);
            float2 p1 = unpack2(acc2[i][2 * j + 1]);
            float4 v;
            v.x = p0.x * SCALE_; v.y = p0.y * SCALE_;
            v.z = p1.x * SCALE_; v.w = p1.y * SCALE_;
            *(float4*)(row + j * 4) = v;
        }
    }
}

// ---------------- v transpose: g_vt[b][d][n] = qkv[b][n][256+d] ----------------
__global__ void __launch_bounds__(256) vtrans_k() {
    __shared__ float ts[32][33];
    int b = blockIdx.x >> 3, dt = blockIdx.x & 7;
    int tid = threadIdx.x;
    const float* src = g_qkv + (size_t)b * N_ * 768 + 256 + dt * 32;
    float* dst = g_vt + ((size_t)b * 256 + dt * 32) * 128;
    for (int nt = 0; nt < 4; nt++) {
        int nn = tid >> 3, dd4 = (tid & 7) * 4;
        float4 vv = *(const float4*)(src + (size_t)(nt * 32 + nn) * 768 + dd4);
        ts[dd4 + 0][nn] = vv.x; ts[dd4 + 1][nn] = vv.y;
        ts[dd4 + 2][nn] = vv.z; ts[dd4 + 3][nn] = vv.w;
        __syncthreads();
        int dd = tid >> 5, n2 = tid & 31;
#pragma unroll
        for (int r = 0; r < 4; r++)
            dst[(size_t)(dd + r * 8) * 128 + nt * 32 + n2] = ts[dd + r * 8][n2];
        __syncthreads();
    }
}

// ---------------- bdot[row] = SCALE * (bmlp . logit_k[row]) ----------------
__global__ void bdot_k(const float* __restrict__ bmlp) {
    int w = threadIdx.x >> 5, l = threadIdx.x & 31;
    int row = blockIdx.x * 8 + w;
    const float* lk = g_qkv + (size_t)row * 768 + 512;
    float acc = 0.f;
#pragma unroll
    for (int j = 0; j < 8; j++) acc = fmaf(bmlp[l + 32 * j], lk[l + 32 * j], acc);
#pragma unroll
    for (int o = 16; o; o >>= 1) acc += __shfl_xor_sync(0xffffffffu, acc, o);
    if (l == 0) g_bdot[row] = acc * SCALE_;
}

// ---------------- sequential greedy decode: 1 CTA (512 thr) per batch ----------------
// R11 structure; MRC=8; lse/logf runs ONLY on warp 8 (overlaps warps 0-7's
// P-row DRAM wait); out written by tid 256.
__global__ void __launch_bounds__(512, 1) decode_k(float* __restrict__ out) {
    extern __shared__ __align__(16) float dyn_s[];
    float4* Ms4T = (float4*)dyn_s;                   // [64 u][MTU], n contiguous

    __shared__ __align__(16) float attn_s[H_ * 132]; // [h][n], +4 pad at n>=64
    __shared__ __align__(16) float ctx_s[E_];
    __shared__ float lp_part[4][N_];
    __shared__ float logits_s[N_];
    __shared__ float bd_s[N_];

    int b = blockIdx.x, tid = threadIdx.x;
    int w = tid >> 5, l = tid & 31;
    int nL = tid & 127, pL = tid >> 7;

    const float4* Mb4 = (const float4*)(g_M + (size_t)b * N_ * E_);
    const float4* Pb = (const float4*)(g_P + (size_t)b * N_ * 1024);

    // ---- stage M transposed: Ms4T[u][n] = M[n][u] ----
    for (int idx = tid; idx < N_ * 64; idx += 512) {
        int n = idx >> 6, u = idx & 63;
        Ms4T[u * MTU + n] = Mb4[n * 64 + u];
    }
    // ---- register cache: first MRC float4 of this thread's M slice (as pairs) ----
    u64 Mreg2[2 * MRC];
#pragma unroll
    for (int i = 0; i < MRC; i++) {
        ulonglong2 t = *(const ulonglong2*)(Mb4 + nL * 64 + pL * 16 + i);
        Mreg2[2 * i] = t.x; Mreg2[2 * i + 1] = t.y;
    }

    // ---- stage v into regs as packed pairs: thread t holds v[nh*64+i][d] ----
    u64 v2[32];
    {
        int d = tid >> 1, nh = tid & 1;
        const ulonglong2* vb2 = (const ulonglong2*)(g_vt + ((size_t)b * 256 + d) * 128 + nh * 64);
#pragma unroll
        for (int i = 0; i < 16; i++) {
            ulonglong2 t = vb2[i];
            v2[2 * i] = t.x; v2[2 * i + 1] = t.y;
        }
    }
    if (tid < N_) bd_s[tid] = g_bdot[b * N_ + tid];
    __syncthreads();

    // register state (redundant per thread)
    unsigned visA = (l == 0) ? 1u : 0u;              // bits 0..3 for n = 4l..4l+3
    unsigned visD = (l == 0) ? 1u : 0u;              // bit j for n = l + 32j
    float lp = 0.f;                                  // meaningful on warp 8 only

    // prime: P row for cur = 0
    float4 pv;
    if (w < 8) pv = Pb[0 * 256 + w * 32 + l];

    for (int step = 0; step < N_ - 1; step++) {
        // ---- A: warps 0..7 = heads; lane l owns n = 4l..4l+3 ----
        if (w < 8) {
            int n0 = 4 * l;
            float a0 = (visA & 1u) ? NEGV : pv.x;
            float a1 = (visA & 2u) ? NEGV : pv.y;
            float a2 = (visA & 4u) ? NEGV : pv.z;
            float a3 = (visA & 8u) ? NEGV : pv.w;
            float m = fmaxf(fmaxf(a0, a1), fmaxf(a2, a3));
#pragma unroll
            for (int o = 16; o; o >>= 1) m = fmaxf(m, __shfl_xor_sync(0xffffffffu, m, o));
            a0 = expf(a0 - m); a1 = expf(a1 - m); a2 = expf(a2 - m); a3 = expf(a3 - m);
            float ssum = a0 + a1 + a2 + a3;
#pragma unroll
            for (int o = 16; o; o >>= 1) ssum += __shfl_xor_sync(0xffffffffu, ssum, o);
            float inv = 1.0f / ssum;
            float4 wv;
            wv.x = a0 * inv; wv.y = a1 * inv; wv.z = a2 * inv; wv.w = a3 * inv;
            *(float4*)&attn_s[w * 132 + n0 + 4 * (l >= 16)] = wv;
        }
        __syncthreads();

        // ---- B: ctx[d] = sum_n attn[h(d)][n] * v[n][d]  (packed FFMA2) ----
        {
            int d = tid >> 1, nh = tid & 1, hh = d >> 5;
            const ulonglong2* ap2 = (const ulonglong2*)(attn_s + hh * 132 + nh * 68);
            u64 acc2 = 0ULL;
#pragma unroll
            for (int i = 0; i < 16; i++) {
                ulonglong2 av = ap2[i];
                ffma2(acc2, av.x, v2[2 * i]);
                ffma2(acc2, av.y, v2[2 * i + 1]);
            }
            float2 ac = unpack2(acc2);
            float acc = ac.x + ac.y;
            acc += __shfl_xor_sync(0xffffffffu, acc, 1);
            if (!nh) ctx_s[d] = acc;
        }
        __syncthreads();

        // ---- C: logits partials (packed FFMA2; first MRC float4 from regs) ----
        {
            const ulonglong2* c2 = (const ulonglong2*)ctx_s + pL * 16;
            const ulonglong2* mr = (const ulonglong2*)Ms4T + (pL * 16) * MTU + nL;
            u64 sA = 0ULL, sB = 0ULL;
#pragma unroll
            for (int i = 0; i < MRC; i++) {
                ulonglong2 c = c2[i];
                ffma2(sA, Mreg2[2 * i], c.x);
                ffma2(sB, Mreg2[2 * i + 1], c.y);
            }
#pragma unroll
            for (int i = MRC; i < 16; i++) {
                ulonglong2 mv = mr[i * MTU];
                ulonglong2 c = c2[i];
                ffma2(sA, mv.x, c.x);
                ffma2(sB, mv.y, c.y);
            }
            float2 a = unpack2(sA), bq = unpack2(sB);
            lp_part[pL][nL] = (a.x + a.y) + (bq.x + bq.y);
        }
        __syncthreads();

        // ---- D: tid<128 (n = tid): sum partials, one tanhf, mask -> logits_s ----
        if (tid < N_) {
            float s = lp_part[0][tid] + lp_part[1][tid] + lp_part[2][tid] + lp_part[3][tid];
            float lg = tanhf(fmaf(SCALE_, s, bd_s[tid])) * CLIPV;
            if ((visD >> w) & 1u) lg = NEGV;         // w<4, n = 32w + l, visD bit w
            logits_s[tid] = lg;
        }
        __syncthreads();

        // ---- E: argmax (all warps) -> state -> next P load; lse on warp 8 only ----
        {
            float lv[4];
            float bv = -3.0e38f; int bi = 0;
#pragma unroll
            for (int j = 0; j < 4; j++) {
                lv[j] = logits_s[l + 32 * j];
                if (lv[j] > bv) { bv = lv[j]; bi = l + 32 * j; }
            }
#pragma unroll
            for (int o = 16; o; o >>= 1) {
                float ov = __shfl_xor_sync(0xffffffffu, bv, o);
                int oi = __shfl_xor_sync(0xffffffffu, bi, o);
                if (ov > bv || (ov == bv && oi < bi)) { bv = ov; bi = oi; }
            }
            // state update + immediately issue next P row load
            if ((bi >> 2) == l) visA |= 1u << (bi & 3);
            if ((bi & 31) == l) visD |= 1u << (bi >> 5);
            if (w < 8) pv = Pb[(size_t)bi * 256 + w * 32 + l];

            // lse + logp only on warp 8 (hidden under warps 0-7's P-row wait)
            if (w == 8) {
                float es = 0.f;
#pragma unroll
                for (int j = 0; j < 4; j++) es += expf(lv[j] - bv);
#pragma unroll
                for (int o = 16; o; o >>= 1) es += __shfl_xor_sync(0xffffffffu, es, o);
                lp -= logf(es);
            }
        }
        // no trailing barrier: bar1..bar4 of the next step order all smem reuse
    }

    if (tid == 256) out[b] = lp;   // warp 8, lane 0
}

// ---------------- host launch ----------------
extern "C" void kernel_launch(void* const* d_in, const int* in_sizes, int n_in,
                              void* d_out, int out_size) {
    const float* ne    = (const float*)d_in[0];
    const float* Wqkv  = (const float*)d_in[1];
    const float* bqkv  = (const float*)d_in[2];
    const float* Wfix  = (const float*)d_in[3];
    const float* bfix  = (const float*)d_in[4];
    const float* Wstep = (const float*)d_in[5];
    const float* bstep = (const float*)d_in[6];
    const float* Wmlp  = (const float*)d_in[7];
    const float* bmlp  = (const float*)d_in[8];
    float* out = (float*)d_out;

    float *p_qkv = nullptr, *p_Qc = nullptr, *p_M = nullptr, *p_P = nullptr;
    cudaGetSymbolAddress((void**)&p_qkv, g_qkv);
    cudaGetSymbolAddress((void**)&p_Qc, g_Qc);
    cudaGetSymbolAddress((void**)&p_M, g_M);
    cudaGetSymbolAddress((void**)&p_P, g_P);

    size_t dec_smem = (size_t)64 * MTU * sizeof(float4);   // 132096
    cudaFuncSetAttribute(decode_k, cudaFuncAttributeMaxDynamicSharedMemorySize,
                         (int)dec_smem);

    mean_k<<<B_, E_>>>(ne);
    qfirst_k<<<B_, E_>>>(ne, Wfix, bfix, Wstep, bstep);

    sgemm_k<0><<<dim3(768 / 128, (B_ * N_) / 128), 256>>>(ne, Wqkv, bqkv, p_qkv,
                                                          E_, E_, 768, 768);
    sgemm_k<0><<<dim3(E_ / 128, (B_ * N_) / 128), 256>>>(ne, Wstep + 256 * 256, nullptr,
                                                         p_Qc, E_, E_, E_, E_);
    sgemm_k<1><<<dim3(E_ / 128, (B_ * N_) / 128), 256>>>(p_qkv + 512, Wmlp, nullptr,
                                                         p_M, E_, 768, E_, E_);
    pmat_k<<<B_ * H_, 256>>>(p_P);
    vtrans_k<<<B_ * 8, 256>>>();
    bdot_k<<<(B_ * N_) / 8, 256>>>(bmlp);

    decode_k<<<B_, 512, dec_smem>>>(out);
}

// round 13
// speedup vs baseline: 1.4857x; 1.4857x over previous
#include <cuda_runtime.h>
#include <math.h>

#define B_ 512
#define N_ 128
#define E_ 256
#define H_ 8
#define D_ 32
#define SCALE_ 0.17677669529663687f  /* 1/sqrt(32) */
#define NEGV  (-1000000000.0f)
#define CLIPV 10.0f
#define MTU   129                    /* Ms4T row stride in float4 units */
#define MRC   6                      /* M float4s cached in registers per thread */

typedef unsigned long long u64;

// packed fp32x2 FMA: d = a*b + d  (elementwise on (lo,hi))
__device__ __forceinline__ void ffma2(u64& d, u64 a, u64 b) {
    asm("fma.rn.f32x2 %0, %1, %2, %0;" : "+l"(d) : "l"(a), "l"(b));
}
__device__ __forceinline__ u64 pack2(float x, float y) {
    u64 r; asm("mov.b64 %0, {%1, %2};" : "=l"(r) : "f"(x), "f"(y)); return r;
}
__device__ __forceinline__ float2 unpack2(u64 v) {
    float2 r; asm("mov.b64 {%0, %1}, %2;" : "=f"(r.x), "=f"(r.y) : "l"(v)); return r;
}

// ---------------- scratch (device globals; no allocation) ----------------
__device__ float g_qkv[(size_t)B_ * N_ * 768];   // k | v | logit_k
__device__ float g_Qc [(size_t)B_ * N_ * E_];    // X @ Wstep_bot
__device__ float g_M  [(size_t)B_ * N_ * E_];    // logit_k @ Wmlp^T
__device__ float g_P  [(size_t)B_ * N_ * 1024];  // precomputed attn logits [b][i][h][n]
__device__ float g_vt [(size_t)B_ * E_ * N_];    // v transposed [b][d][n]
__device__ float g_bdot[B_ * N_];
__device__ float g_ge [B_ * E_];
__device__ float g_qf [B_ * E_];

// ---------------- graph_emb = mean over nodes ----------------
__global__ void mean_k(const float* __restrict__ ne) {
    int b = blockIdx.x, e = threadIdx.x;
    const float* p = ne + (size_t)b * N_ * E_ + e;
    float s = 0.f;
#pragma unroll 8
    for (int n = 0; n < N_; n++) s += p[(size_t)n * E_];
    g_ge[b * E_ + e] = s * (1.0f / N_);
}

// ---------------- q_first = ge@Wfix + first@Wstep_top + bfix + bstep ----------------
__global__ void qfirst_k(const float* __restrict__ ne,
                         const float* __restrict__ Wfix, const float* __restrict__ bfix,
                         const float* __restrict__ Wstep, const float* __restrict__ bstep) {
    __shared__ float ge_s[E_], fi_s[E_];
    int b = blockIdx.x, t = threadIdx.x;
    ge_s[t] = g_ge[b * E_ + t];
    fi_s[t] = ne[(size_t)b * N_ * E_ + t];
    __syncthreads();
    float acc = bfix[t] + bstep[t];
#pragma unroll 4
    for (int f = 0; f < E_; f++) {
        acc = fmaf(ge_s[f], Wfix[f * E_ + t], acc);
        acc = fmaf(fi_s[f], Wstep[f * E_ + t], acc);
    }
    g_qf[b * E_ + t] = acc;
}

// ---------------- generic fp32 GEMM: C = A(MxK)*B(KxN) [+bias] ----------------
// Single-buffer, BK=16 (half the barriers of BK=8), FFMA2 core. K % 16 == 0.
template <int TRANSB>
__global__ void __launch_bounds__(256) sgemm_k(
    const float* __restrict__ A, const float* __restrict__ Bm,
    const float* __restrict__ bias, float* __restrict__ C,
    int K, int lda, int ldb, int ldc) {
    __shared__ __align__(16) float As[16][128];
    __shared__ __align__(16) float Bs[16][128];
    int tid = threadIdx.x;
    int tx = tid & 15, ty = tid >> 4;
    int rowBase = blockIdx.y * 128;
    int colBase = blockIdx.x * 128;

    u64 acc2[8][4];
#pragma unroll
    for (int i = 0; i < 8; i++)
#pragma unroll
        for (int j = 0; j < 4; j++) acc2[i][j] = 0ULL;

    int aR = tid >> 1;              // 0..127
    int aC = (tid & 1) * 8;         // 0 or 8
    int bK_n = tid >> 4;            // 0..15   (normal B)
    int bC_n = (tid & 15) * 8;
    int bCol_t = tid & 127;         // trans B
    int bK_t = (tid >> 7) * 8;      // 0 or 8

    for (int kt = 0; kt < K; kt += 16) {
#pragma unroll
        for (int p = 0; p < 2; p++) {
            float4 av = *(const float4*)(A + (size_t)(rowBase + aR) * lda + kt + aC + p * 4);
            As[aC + p * 4 + 0][aR] = av.x; As[aC + p * 4 + 1][aR] = av.y;
            As[aC + p * 4 + 2][aR] = av.z; As[aC + p * 4 + 3][aR] = av.w;
        }
        if (!TRANSB) {
            float4 b0 = *(const float4*)(Bm + (size_t)(kt + bK_n) * ldb + colBase + bC_n);
            float4 b1 = *(const float4*)(Bm + (size_t)(kt + bK_n) * ldb + colBase + bC_n + 4);
            *(float4*)&Bs[bK_n][bC_n] = b0;
            *(float4*)&Bs[bK_n][bC_n + 4] = b1;
        } else {
#pragma unroll
            for (int p = 0; p < 2; p++) {
                float4 bv = *(const float4*)(Bm + (size_t)(colBase + bCol_t) * ldb + kt + bK_t + p * 4);
                Bs[bK_t + p * 4 + 0][bCol_t] = bv.x; Bs[bK_t + p * 4 + 1][bCol_t] = bv.y;
                Bs[bK_t + p * 4 + 2][bCol_t] = bv.z; Bs[bK_t + p * 4 + 3][bCol_t] = bv.w;
            }
        }
        __syncthreads();
#pragma unroll
        for (int kk = 0; kk < 16; kk++) {
            float ra[8];
            u64 rb2[4];
            *(float4*)&ra[0] = *(const float4*)&As[kk][ty * 8];
            *(float4*)&ra[4] = *(const float4*)&As[kk][ty * 8 + 4];
            {
                ulonglong2 t0 = *(const ulonglong2*)&Bs[kk][tx * 8];
                ulonglong2 t1 = *(const ulonglong2*)&Bs[kk][tx * 8 + 4];
                rb2[0] = t0.x; rb2[1] = t0.y; rb2[2] = t1.x; rb2[3] = t1.y;
            }
#pragma unroll
            for (int i = 0; i < 8; i++) {
                u64 raa = pack2(ra[i], ra[i]);
#pragma unroll
                for (int j = 0; j < 4; j++) ffma2(acc2[i][j], raa, rb2[j]);
            }
        }
        __syncthreads();
    }
#pragma unroll
    for (int i = 0; i < 8; i++) {
        int r = rowBase + ty * 8 + i;
#pragma unroll
        for (int j = 0; j < 2; j++) {
            int c = colBase + tx * 8 + j * 4;
            float2 p0 = unpack2(acc2[i][2 * j + 0]);
            float2 p1 = unpack2(acc2[i][2 * j + 1]);
            float4 v;
            v.x = p0.x; v.y = p0.y; v.z = p1.x; v.w = p1.y;
            if (bias) { v.x += bias[c]; v.y += bias[c + 1]; v.z += bias[c + 2]; v.w += bias[c + 3]; }
            *(float4*)(C + (size_t)r * ldc + c) = v;
        }
    }
}

// ---------------- P[b][i][h][n] = SCALE * (qf[b]+Qc[b][i])_h . k[b][n]_h ----------------
__global__ void __launch_bounds__(256) pmat_k(float* __restrict__ P) {
    __shared__ __align__(16) float kt[32][132];
    __shared__ __align__(16) float qt[32][132];
    int h = blockIdx.x & 7, b = blockIdx.x >> 3;
    int tid = threadIdx.x;
    const float* kb  = g_qkv + (size_t)b * N_ * 768 + h * 32;
    const float* qcb = g_Qc  + (size_t)b * N_ * 256 + h * 32;
    const float* qfb = g_qf  + b * 256 + h * 32;

    for (int idx = tid; idx < N_ * 8; idx += 256) {
        int n = idx >> 3, d4 = (idx & 7) * 4;
        float4 kv  = *(const float4*)(kb  + (size_t)n * 768 + d4);
        float4 qv  = *(const float4*)(qcb + (size_t)n * 256 + d4);
        float4 qf4 = *(const float4*)(qfb + d4);
        kt[d4 + 0][n] = kv.x; kt[d4 + 1][n] = kv.y;
        kt[d4 + 2][n] = kv.z; kt[d4 + 3][n] = kv.w;
        qt[d4 + 0][n] = qv.x + qf4.x; qt[d4 + 1][n] = qv.y + qf4.y;
        qt[d4 + 2][n] = qv.z + qf4.z; qt[d4 + 3][n] = qv.w + qf4.w;
    }
    __syncthreads();

    int tx = tid & 15, ty = tid >> 4;
    u64 acc2[8][4];
#pragma unroll
    for (int i = 0; i < 8; i++)
#pragma unroll
        for (int j = 0; j < 4; j++) acc2[i][j] = 0ULL;

#pragma unroll 4
    for (int d = 0; d < 32; d++) {
        float ra[8];
        u64 rb2[4];
        *(float4*)&ra[0] = *(const float4*)&qt[d][ty * 8];
        *(float4*)&ra[4] = *(const float4*)&qt[d][ty * 8 + 4];
        {
            ulonglong2 t0 = *(const ulonglong2*)&kt[d][tx * 8];
            ulonglong2 t1 = *(const ulonglong2*)&kt[d][tx * 8 + 4];
            rb2[0] = t0.x; rb2[1] = t0.y; rb2[2] = t1.x; rb2[3] = t1.y;
        }
#pragma unroll
        for (int i = 0; i < 8; i++) {
            u64 raa = pack2(ra[i], ra[i]);
#pragma unroll
            for (int j = 0; j < 4; j++) ffma2(acc2[i][j], raa, rb2[j]);
        }
    }

#pragma unroll
    for (int i = 0; i < 8; i++) {
        float* row = P + ((size_t)(b * N_ + ty * 8 + i)) * 1024 + h * 128 + tx * 8;
#pragma unroll
        for (int j = 0; j < 2; j++) {
            float2 p0 = unpack2(acc2[i][2 * j + 0]);
            float2 p1 = unpack2(acc2[i][2 * j + 1]);
            float4 v;
            v.x = p0.x * SCALE_; v.y = p0.y * SCALE_;
            v.z = p1.x * SCALE_; v.w = p1.y * SCALE_;
            *(float4*)(row + j * 4) = v;
        }
    }
}

// ---------------- v transpose: g_vt[b][d][n] = qkv[b][n][256+d] ----------------
__global__ void __launch_bounds__(256) vtrans_k() {
    __shared__ float ts[32][33];
    int b = blockIdx.x >> 3, dt = blockIdx.x & 7;
    int tid = threadIdx.x;
    const float* src = g_qkv + (size_t)b * N_ * 768 + 256 + dt * 32;
    float* dst = g_vt + ((size_t)b * 256 + dt * 32) * 128;
    for (int nt = 0; nt < 4; nt++) {
        int nn = tid >> 3, dd4 = (tid & 7) * 4;
        float4 vv = *(const float4*)(src + (size_t)(nt * 32 + nn) * 768 + dd4);
        ts[dd4 + 0][nn] = vv.x; ts[dd4 + 1][nn] = vv.y;
        ts[dd4 + 2][nn] = vv.z; ts[dd4 + 3][nn] = vv.w;
        __syncthreads();
        int dd = tid >> 5, n2 = tid & 31;
#pragma unroll
        for (int r = 0; r < 4; r++)
            dst[(size_t)(dd + r * 8) * 128 + nt * 32 + n2] = ts[dd + r * 8][n2];
        __syncthreads();
    }
}

// ---------------- bdot[row] = SCALE * (bmlp . logit_k[row]) ----------------
__global__ void bdot_k(const float* __restrict__ bmlp) {
    int w = threadIdx.x >> 5, l = threadIdx.x & 31;
    int row = blockIdx.x * 8 + w;
    const float* lk = g_qkv + (size_t)row * 768 + 512;
    float acc = 0.f;
#pragma unroll
    for (int j = 0; j < 8; j++) acc = fmaf(bmlp[l + 32 * j], lk[l + 32 * j], acc);
#pragma unroll
    for (int o = 16; o; o >>= 1) acc += __shfl_xor_sync(0xffffffffu, acc, o);
    if (l == 0) g_bdot[row] = acc * SCALE_;
}

// ---------------- sequential greedy decode: 1 CTA (512 thr) per batch ----------------
// R11 structure (MRC=6, no spills). Phase E runs on warps 0-8 only
// (visA consumers: warps 0-7; visD consumers: warps 0-3; lse/lp: warp 8).
__global__ void __launch_bounds__(512, 1) decode_k(float* __restrict__ out) {
    extern __shared__ __align__(16) float dyn_s[];
    float4* Ms4T = (float4*)dyn_s;                   // [64 u][MTU], n contiguous

    __shared__ __align__(16) float attn_s[H_ * 132]; // [h][n], +4 pad at n>=64
    __shared__ __align__(16) float ctx_s[E_];
    __shared__ float lp_part[4][N_];
    __shared__ float logits_s[N_];
    __shared__ float bd_s[N_];

    int b = blockIdx.x, tid = threadIdx.x;
    int w = tid >> 5, l = tid & 31;
    int nL = tid & 127, pL = tid >> 7;

    const float4* Mb4 = (const float4*)(g_M + (size_t)b * N_ * E_);
    const float4* Pb = (const float4*)(g_P + (size_t)b * N_ * 1024);

    // ---- stage M transposed: Ms4T[u][n] = M[n][u] ----
    for (int idx = tid; idx < N_ * 64; idx += 512) {
        int n = idx >> 6, u = idx & 63;
        Ms4T[u * MTU + n] = Mb4[n * 64 + u];
    }
    // ---- register cache: first MRC float4 of this thread's M slice (as pairs) ----
    u64 Mreg2[2 * MRC];
#pragma unroll
    for (int i = 0; i < MRC; i++) {
        ulonglong2 t = *(const ulonglong2*)(Mb4 + nL * 64 + pL * 16 + i);
        Mreg2[2 * i] = t.x; Mreg2[2 * i + 1] = t.y;
    }

    // ---- stage v into regs as packed pairs: thread t holds v[nh*64+i][d] ----
    u64 v2[32];
    {
        int d = tid >> 1, nh = tid & 1;
        const ulonglong2* vb2 = (const ulonglong2*)(g_vt + ((size_t)b * 256 + d) * 128 + nh * 64);
#pragma unroll
        for (int i = 0; i < 16; i++) {
            ulonglong2 t = vb2[i];
            v2[2 * i] = t.x; v2[2 * i + 1] = t.y;
        }
    }
    if (tid < N_) bd_s[tid] = g_bdot[b * N_ + tid];
    __syncthreads();

    // register state (redundant per thread on warps 0-8)
    unsigned visA = (l == 0) ? 1u : 0u;              // bits 0..3 for n = 4l..4l+3
    unsigned visD = (l == 0) ? 1u : 0u;              // bit j for n = l + 32j
    float lp = 0.f;                                  // meaningful on warp 8 only

    // prime: P row for cur = 0
    float4 pv;
    if (w < 8) pv = Pb[0 * 256 + w * 32 + l];

    for (int step = 0; step < N_ - 1; step++) {
        // ---- A: warps 0..7 = heads; lane l owns n = 4l..4l+3 ----
        if (w < 8) {
            int n0 = 4 * l;
            float a0 = (visA & 1u) ? NEGV : pv.x;
            float a1 = (visA & 2u) ? NEGV : pv.y;
            float a2 = (visA & 4u) ? NEGV : pv.z;
            float a3 = (visA & 8u) ? NEGV : pv.w;
            float m = fmaxf(fmaxf(a0, a1), fmaxf(a2, a3));
#pragma unroll
            for (int o = 16; o; o >>= 1) m = fmaxf(m, __shfl_xor_sync(0xffffffffu, m, o));
            a0 = expf(a0 - m); a1 = expf(a1 - m); a2 = expf(a2 - m); a3 = expf(a3 - m);
            float ssum = a0 + a1 + a2 + a3;
#pragma unroll
            for (int o = 16; o; o >>= 1) ssum += __shfl_xor_sync(0xffffffffu, ssum, o);
            float inv = 1.0f / ssum;
            float4 wv;
            wv.x = a0 * inv; wv.y = a1 * inv; wv.z = a2 * inv; wv.w = a3 * inv;
            *(float4*)&attn_s[w * 132 + n0 + 4 * (l >= 16)] = wv;
        }
        __syncthreads();

        // ---- B: ctx[d] = sum_n attn[h(d)][n] * v[n][d]  (packed FFMA2) ----
        {
            int d = tid >> 1, nh = tid & 1, hh = d >> 5;
            const ulonglong2* ap2 = (const ulonglong2*)(attn_s + hh * 132 + nh * 68);
            u64 acc2 = 0ULL;
#pragma unroll
            for (int i = 0; i < 16; i++) {
                ulonglong2 av = ap2[i];
                ffma2(acc2, av.x, v2[2 * i]);
                ffma2(acc2, av.y, v2[2 * i + 1]);
            }
            float2 ac = unpack2(acc2);
            float acc = ac.x + ac.y;
            acc += __shfl_xor_sync(0xffffffffu, acc, 1);
            if (!nh) ctx_s[d] = acc;
        }
        __syncthreads();

        // ---- C: logits partials (packed FFMA2; first MRC float4 from regs) ----
        {
            const ulonglong2* c2 = (const ulonglong2*)ctx_s + pL * 16;
            const ulonglong2* mr = (const ulonglong2*)Ms4T + (pL * 16) * MTU + nL;
            u64 sA = 0ULL, sB = 0ULL;
#pragma unroll
            for (int i = 0; i < MRC; i++) {
                ulonglong2 c = c2[i];
                ffma2(sA, Mreg2[2 * i], c.x);
                ffma2(sB, Mreg2[2 * i + 1], c.y);
            }
#pragma unroll
            for (int i = MRC; i < 16; i++) {
                ulonglong2 mv = mr[i * MTU];
                ulonglong2 c = c2[i];
                ffma2(sA, mv.x, c.x);
                ffma2(sB, mv.y, c.y);
            }
            float2 a = unpack2(sA), bq = unpack2(sB);
            lp_part[pL][nL] = (a.x + a.y) + (bq.x + bq.y);
        }
        __syncthreads();

        // ---- D: tid<128 (n = tid): sum partials, one tanhf, mask -> logits_s ----
        if (tid < N_) {
            float s = lp_part[0][tid] + lp_part[1][tid] + lp_part[2][tid] + lp_part[3][tid];
            float lg = tanhf(fmaf(SCALE_, s, bd_s[tid])) * CLIPV;
            if ((visD >> w) & 1u) lg = NEGV;         // w<4, n = 32w + l, visD bit w
            logits_s[tid] = lg;
        }
        __syncthreads();

        // ---- E: warps 0-8 only: argmax -> state -> next P load; lse on warp 8 ----
        if (w <= 8) {
            float lv[4];
            float bv = -3.0e38f; int bi = 0;
#pragma unroll
            for (int j = 0; j < 4; j++) {
                lv[j] = logits_s[l + 32 * j];
                if (lv[j] > bv) { bv = lv[j]; bi = l + 32 * j; }
            }
#pragma unroll
            for (int o = 16; o; o >>= 1) {
                float ov = __shfl_xor_sync(0xffffffffu, bv, o);
                int oi = __shfl_xor_sync(0xffffffffu, bi, o);
                if (ov > bv || (ov == bv && oi < bi)) { bv = ov; bi = oi; }
            }
            // state update + immediately issue next P row load
            if ((bi >> 2) == l) visA |= 1u << (bi & 3);
            if ((bi & 31) == l) visD |= 1u << (bi >> 5);
            if (w < 8) pv = Pb[(size_t)bi * 256 + w * 32 + l];

            // lse + logp only on warp 8 (hidden under warps 0-7's P-row wait)
            if (w == 8) {
                float es = 0.f;
#pragma unroll
                for (int j = 0; j < 4; j++) es += expf(lv[j] - bv);
#pragma unroll
                for (int o = 16; o; o >>= 1) es += __shfl_xor_sync(0xffffffffu, es, o);
                lp -= logf(es);
            }
        }
        // no trailing barrier: bar1..bar4 of the next step order all smem reuse
    }

    if (tid == 256) out[b] = lp;   // warp 8, lane 0
}

// ---------------- host launch ----------------
extern "C" void kernel_launch(void* const* d_in, const int* in_sizes, int n_in,
                              void* d_out, int out_size) {
    const float* ne    = (const float*)d_in[0];
    const float* Wqkv  = (const float*)d_in[1];
    const float* bqkv  = (const float*)d_in[2];
    const float* Wfix  = (const float*)d_in[3];
    const float* bfix  = (const float*)d_in[4];
    const float* Wstep = (const float*)d_in[5];
    const float* bstep = (const float*)d_in[6];
    const float* Wmlp  = (const float*)d_in[7];
    const float* bmlp  = (const float*)d_in[8];
    float* out = (float*)d_out;

    float *p_qkv = nullptr, *p_Qc = nullptr, *p_M = nullptr, *p_P = nullptr;
    cudaGetSymbolAddress((void**)&p_qkv, g_qkv);
    cudaGetSymbolAddress((void**)&p_Qc, g_Qc);
    cudaGetSymbolAddress((void**)&p_M, g_M);
    cudaGetSymbolAddress((void**)&p_P, g_P);

    size_t dec_smem = (size_t)64 * MTU * sizeof(float4);   // 132096
    cudaFuncSetAttribute(decode_k, cudaFuncAttributeMaxDynamicSharedMemorySize,
                         (int)dec_smem);

    mean_k<<<B_, E_>>>(ne);
    qfirst_k<<<B_, E_>>>(ne, Wfix, bfix, Wstep, bstep);

    sgemm_k<0><<<dim3(768 / 128, (B_ * N_) / 128), 256>>>(ne, Wqkv, bqkv, p_qkv,
                                                          E_, E_, 768, 768);
    sgemm_k<0><<<dim3(E_ / 128, (B_ * N_) / 128), 256>>>(ne, Wstep + 256 * 256, nullptr,
                                                         p_Qc, E_, E_, E_, E_);
    sgemm_k<1><<<dim3(E_ / 128, (B_ * N_) / 128), 256>>>(p_qkv + 512, Wmlp, nullptr,
                                                         p_M, E_, 768, E_, E_);
    pmat_k<<<B_ * H_, 256>>>(p_P);
    vtrans_k<<<B_ * 8, 256>>>();
    bdot_k<<<(B_ * N_) / 8, 256>>>(bmlp);

    decode_k<<<B_, 512, dec_smem>>>(out);
}

// round 14
// speedup vs baseline: 1.5254x; 1.0267x over previous
#include <cuda_runtime.h>
#include <math.h>

#define B_ 512
#define N_ 128
#define E_ 256
#define H_ 8
#define D_ 32
#define SCALE_ 0.17677669529663687f  /* 1/sqrt(32) */
#define NEGV  (-1000000000.0f)
#define CLIPV 10.0f
#define MTU   129                    /* Ms4T row stride in float4 units */
#define MRC   6                      /* M float4s cached in registers per thread */

typedef unsigned long long u64;

// packed fp32x2 FMA: d = a*b + d  (elementwise on (lo,hi))
__device__ __forceinline__ void ffma2(u64& d, u64 a, u64 b) {
    asm("fma.rn.f32x2 %0, %1, %2, %0;" : "+l"(d) : "l"(a), "l"(b));
}
__device__ __forceinline__ u64 pack2(float x, float y) {
    u64 r; asm("mov.b64 %0, {%1, %2};" : "=l"(r) : "f"(x), "f"(y)); return r;
}
__device__ __forceinline__ float2 unpack2(u64 v) {
    float2 r; asm("mov.b64 {%0, %1}, %2;" : "=f"(r.x), "=f"(r.y) : "l"(v)); return r;
}
__device__ __forceinline__ void cp_async16(unsigned smem_addr, const void* gptr) {
    asm volatile("cp.async.cg.shared.global [%0], [%1], 16;"
                 :: "r"(smem_addr), "l"(gptr));
}

// ---------------- scratch (device globals; no allocation) ----------------
__device__ float g_qkv[(size_t)B_ * N_ * 768];   // k | v | logit_k
__device__ float g_Qc [(size_t)B_ * N_ * E_];    // X @ Wstep_bot
__device__ float g_M  [(size_t)B_ * N_ * E_];    // logit_k @ Wmlp^T
__device__ float g_P  [(size_t)B_ * N_ * 1024];  // precomputed attn logits [b][i][h][n]
__device__ float g_vt [(size_t)B_ * E_ * N_];    // v transposed [b][d][n]
__device__ float g_wt [E_ * E_];                 // Wmlp^T
__device__ float g_bdot[B_ * N_];
__device__ float g_ge [B_ * E_];
__device__ float g_qf [B_ * E_];

// ---------------- graph_emb = mean over nodes ----------------
__global__ void mean_k(const float* __restrict__ ne) {
    int b = blockIdx.x, e = threadIdx.x;
    const float* p = ne + (size_t)b * N_ * E_ + e;
    float s = 0.f;
#pragma unroll 8
    for (int n = 0; n < N_; n++) s += p[(size_t)n * E_];
    g_ge[b * E_ + e] = s * (1.0f / N_);
}

// ---------------- q_first = ge@Wfix + first@Wstep_top + bfix + bstep ----------------
__global__ void qfirst_k(const float* __restrict__ ne,
                         const float* __restrict__ Wfix, const float* __restrict__ bfix,
                         const float* __restrict__ Wstep, const float* __restrict__ bstep) {
    __shared__ float ge_s[E_], fi_s[E_];
    int b = blockIdx.x, t = threadIdx.x;
    ge_s[t] = g_ge[b * E_ + t];
    fi_s[t] = ne[(size_t)b * N_ * E_ + t];
    __syncthreads();
    float acc = bfix[t] + bstep[t];
#pragma unroll 4
    for (int f = 0; f < E_; f++) {
        acc = fmaf(ge_s[f], Wfix[f * E_ + t], acc);
        acc = fmaf(fi_s[f], Wstep[f * E_ + t], acc);
    }
    g_qf[b * E_ + t] = acc;
}

// ---------------- Wmlp transpose: g_wt[j][i] = Wmlp[i][j] ----------------
__global__ void wtrans_k(const float* __restrict__ W) {
    __shared__ float t[32][33];
    int bx = blockIdx.x & 7, by = blockIdx.x >> 3;
    int x = threadIdx.x & 31, y = threadIdx.x >> 5;   // 256 thr: 32x8
#pragma unroll
    for (int r = 0; r < 32; r += 8)
        t[y + r][x] = W[(by * 32 + y + r) * E_ + bx * 32 + x];
    __syncthreads();
#pragma unroll
    for (int r = 0; r < 32; r += 8)
        g_wt[(bx * 32 + y + r) * E_ + by * 32 + x] = t[x][y + r];
}

// ---------------- fp32 GEMM: C = A(MxK)*B(KxN) [+bias] ----------------
// cp.async 3-slot ring, one __syncthreads per 16-K tile, FFMA2 core.
// As row-major [128][16], Bs [16][128]. K % 16 == 0.
__global__ void __launch_bounds__(256) sgemm_k(
    const float* __restrict__ A, const float* __restrict__ Bm,
    const float* __restrict__ bias, float* __restrict__ C,
    int K, int lda, int ldb, int ldc) {
    extern __shared__ __align__(16) float sm[];      // 3 slots x (As 2048 + Bs 2048)
    int tid = threadIdx.x;
    int tx = tid & 15, ty = tid >> 4;
    int rowBase = blockIdx.y * 128;
    int colBase = blockIdx.x * 128;

    u64 acc2[8][4];
#pragma unroll
    for (int i = 0; i < 8; i++)
#pragma unroll
        for (int j = 0; j < 4; j++) acc2[i][j] = 0ULL;

    int arow = tid >> 2, ach = (tid & 3) * 4;        // A: 2 chunks (rows arow, arow+64)
    int bk = tid >> 5, bc = (tid & 31) * 4;          // B: 2 chunks (k-rows bk, bk+8)

    const float* Ab = A + (size_t)rowBase * lda;
    const float* Bb = Bm + colBase;
    unsigned sm_u = (unsigned)__cvta_generic_to_shared(sm);

    int T = K / 16;
    // prologue: tile 0 -> slot 0
    {
        unsigned as_u = sm_u;
        unsigned bs_u = sm_u + 2048 * 4;
        cp_async16(as_u + (arow * 16 + ach) * 4, Ab + (size_t)arow * lda + ach);
        cp_async16(as_u + ((arow + 64) * 16 + ach) * 4, Ab + (size_t)(arow + 64) * lda + ach);
        cp_async16(bs_u + (bk * 128 + bc) * 4, Bb + (size_t)bk * ldb + bc);
        cp_async16(bs_u + ((bk + 8) * 128 + bc) * 4, Bb + (size_t)(bk + 8) * ldb + bc);
        asm volatile("cp.async.commit_group;" ::: "memory");
    }

    for (int t = 0; t < T; t++) {
        if (t + 1 < T) {
            int kt = (t + 1) * 16;
            int slot = (t + 1) % 3;
            unsigned as_u = sm_u + slot * 4096 * 4;
            unsigned bs_u = as_u + 2048 * 4;
            cp_async16(as_u + (arow * 16 + ach) * 4, Ab + (size_t)arow * lda + kt + ach);
            cp_async16(as_u + ((arow + 64) * 16 + ach) * 4,
                       Ab + (size_t)(arow + 64) * lda + kt + ach);
            cp_async16(bs_u + (bk * 128 + bc) * 4, Bb + (size_t)(kt + bk) * ldb + bc);
            cp_async16(bs_u + ((bk + 8) * 128 + bc) * 4, Bb + (size_t)(kt + bk + 8) * ldb + bc);
            asm volatile("cp.async.commit_group;" ::: "memory");
            asm volatile("cp.async.wait_group 1;" ::: "memory");
        } else {
            asm volatile("cp.async.wait_group 0;" ::: "memory");
        }
        __syncthreads();

        const float* As = sm + (t % 3) * 4096;
        const float* Bs = As + 2048;
#pragma unroll
        for (int kk = 0; kk < 16; kk++) {
            u64 rb2[4];
            {
                ulonglong2 t0 = *(const ulonglong2*)&Bs[kk * 128 + tx * 8];
                ulonglong2 t1 = *(const ulonglong2*)&Bs[kk * 128 + tx * 8 + 4];
                rb2[0] = t0.x; rb2[1] = t0.y; rb2[2] = t1.x; rb2[3] = t1.y;
            }
#pragma unroll
            for (int i = 0; i < 8; i++) {
                float a = As[(ty * 8 + i) * 16 + kk];
                u64 raa = pack2(a, a);
#pragma unroll
                for (int j = 0; j < 4; j++) ffma2(acc2[i][j], raa, rb2[j]);
            }
        }
        // one barrier per tile: next iteration's cp.async into slot (t+2)%3 is
        // ordered after every thread's compute on that slot (two syncs back).
    }
#pragma unroll
    for (int i = 0; i < 8; i++) {
        int r = rowBase + ty * 8 + i;
#pragma unroll
        for (int j = 0; j < 2; j++) {
            int c = colBase + tx * 8 + j * 4;
            float2 p0 = unpack2(acc2[i][2 * j + 0]);
            float2 p1 = unpack2(acc2[i][2 * j + 1]);
            float4 v;
            v.x = p0.x; v.y = p0.y; v.z = p1.x; v.w = p1.y;
            if (bias) { v.x += bias[c]; v.y += bias[c + 1]; v.z += bias[c + 2]; v.w += bias[c + 3]; }
            *(float4*)(C + (size_t)r * ldc + c) = v;
        }
    }
}

// ---------------- P[b][i][h][n] = SCALE * (qf[b]+Qc[b][i])_h . k[b][n]_h ----------------
__global__ void __launch_bounds__(256) pmat_k(float* __restrict__ P) {
    __shared__ __align__(16) float kt[32][132];
    __shared__ __align__(16) float qt[32][132];
    int h = blockIdx.x & 7, b = blockIdx.x >> 3;
    int tid = threadIdx.x;
    const float* kb  = g_qkv + (size_t)b * N_ * 768 + h * 32;
    const float* qcb = g_Qc  + (size_t)b * N_ * 256 + h * 32;
    const float* qfb = g_qf  + b * 256 + h * 32;

    for (int idx = tid; idx < N_ * 8; idx += 256) {
        int n = idx >> 3, d4 = (idx & 7) * 4;
        float4 kv  = *(const float4*)(kb  + (size_t)n * 768 + d4);
        float4 qv  = *(const float4*)(qcb + (size_t)n * 256 + d4);
        float4 qf4 = *(const float4*)(qfb + d4);
        kt[d4 + 0][n] = kv.x; kt[d4 + 1][n] = kv.y;
        kt[d4 + 2][n] = kv.z; kt[d4 + 3][n] = kv.w;
        qt[d4 + 0][n] = qv.x + qf4.x; qt[d4 + 1][n] = qv.y + qf4.y;
        qt[d4 + 2][n] = qv.z + qf4.z; qt[d4 + 3][n] = qv.w + qf4.w;
    }
    __syncthreads();

    int tx = tid & 15, ty = tid >> 4;
    u64 acc2[8][4];
#pragma unroll
    for (int i = 0; i < 8; i++)
#pragma unroll
        for (int j = 0; j < 4; j++) acc2[i][j] = 0ULL;

#pragma unroll 4
    for (int d = 0; d < 32; d++) {
        float ra[8];
        u64 rb2[4];
        *(float4*)&ra[0] = *(const float4*)&qt[d][ty * 8];
        *(float4*)&ra[4] = *(const float4*)&qt[d][ty * 8 + 4];
        {
            ulonglong2 t0 = *(const ulonglong2*)&kt[d][tx * 8];
            ulonglong2 t1 = *(const ulonglong2*)&kt[d][tx * 8 + 4];
            rb2[0] = t0.x; rb2[1] = t0.y; rb2[2] = t1.x; rb2[3] = t1.y;
        }
#pragma unroll
        for (int i = 0; i < 8; i++) {
            u64 raa = pack2(ra[i], ra[i]);
#pragma unroll
            for (int j = 0; j < 4; j++) ffma2(acc2[i][j], raa, rb2[j]);
        }
    }

#pragma unroll
    for (int i = 0; i < 8; i++) {
        float* row = P + ((size_t)(b * N_ + ty * 8 + i)) * 1024 + h * 128 + tx * 8;
#pragma unroll
        for (int j = 0; j < 2; j++) {
            float2 p0 = unpack2(acc2[i][2 * j + 0]);
            float2 p1 = unpack2(acc2[i][2 * j + 1]);
            float4 v;
            v.x = p0.x * SCALE_; v.y = p0.y * SCALE_;
            v.z = p1.x * SCALE_; v.w = p1.y * SCALE_;
            *(float4*)(row + j * 4) = v;
        }
    }
}

// ---------------- v transpose: g_vt[b][d][n] = qkv[b][n][256+d] ----------------
__global__ void __launch_bounds__(256) vtrans_k() {
    __shared__ float ts[32][33];
    int b = blockIdx.x >> 3, dt = blockIdx.x & 7;
    int tid = threadIdx.x;
    const float* src = g_qkv + (size_t)b * N_ * 768 + 256 + dt * 32;
    float* dst = g_vt + ((size_t)b * 256 + dt * 32) * 128;
    for (int nt = 0; nt < 4; nt++) {
        int nn = tid >> 3, dd4 = (tid & 7) * 4;
        float4 vv = *(const float4*)(src + (size_t)(nt * 32 + nn) * 768 + dd4);
        ts[dd4 + 0][nn] = vv.x; ts[dd4 + 1][nn] = vv.y;
        ts[dd4 + 2][nn] = vv.z; ts[dd4 + 3][nn] = vv.w;
        __syncthreads();
        int dd = tid >> 5, n2 = tid & 31;
#pragma unroll
        for (int r = 0; r < 4; r++)
            dst[(size_t)(dd + r * 8) * 128 + nt * 32 + n2] = ts[dd + r * 8][n2];
        __syncthreads();
    }
}

// ---------------- bdot[row] = SCALE * (bmlp . logit_k[row]) ----------------
__global__ void bdot_k(const float* __restrict__ bmlp) {
    int w = threadIdx.x >> 5, l = threadIdx.x & 31;
    int row = blockIdx.x * 8 + w;
    const float* lk = g_qkv + (size_t)row * 768 + 512;
    float acc = 0.f;
#pragma unroll
    for (int j = 0; j < 8; j++) acc = fmaf(bmlp[l + 32 * j], lk[l + 32 * j], acc);
#pragma unroll
    for (int o = 16; o; o >>= 1) acc += __shfl_xor_sync(0xffffffffu, acc, o);
    if (l == 0) g_bdot[row] = acc * SCALE_;
}

// ---------------- sequential greedy decode: 1 CTA (512 thr) per batch ----------------
// Unchanged from R13 (MRC=6; phase E on warps 0-8; lse on warp 8).
__global__ void __launch_bounds__(512, 1) decode_k(float* __restrict__ out) {
    extern __shared__ __align__(16) float dyn_s[];
    float4* Ms4T = (float4*)dyn_s;                   // [64 u][MTU], n contiguous

    __shared__ __align__(16) float attn_s[H_ * 132]; // [h][n], +4 pad at n>=64
    __shared__ __align__(16) float ctx_s[E_];
    __shared__ float lp_part[4][N_];
    __shared__ float logits_s[N_];
    __shared__ float bd_s[N_];

    int b = blockIdx.x, tid = threadIdx.x;
    int w = tid >> 5, l = tid & 31;
    int nL = tid & 127, pL = tid >> 7;

    const float4* Mb4 = (const float4*)(g_M + (size_t)b * N_ * E_);
    const float4* Pb = (const float4*)(g_P + (size_t)b * N_ * 1024);

    for (int idx = tid; idx < N_ * 64; idx += 512) {
        int n = idx >> 6, u = idx & 63;
        Ms4T[u * MTU + n] = Mb4[n * 64 + u];
    }
    u64 Mreg2[2 * MRC];
#pragma unroll
    for (int i = 0; i < MRC; i++) {
        ulonglong2 t = *(const ulonglong2*)(Mb4 + nL * 64 + pL * 16 + i);
        Mreg2[2 * i] = t.x; Mreg2[2 * i + 1] = t.y;
    }
    u64 v2[32];
    {
        int d = tid >> 1, nh = tid & 1;
        const ulonglong2* vb2 = (const ulonglong2*)(g_vt + ((size_t)b * 256 + d) * 128 + nh * 64);
#pragma unroll
        for (int i = 0; i < 16; i++) {
            ulonglong2 t = vb2[i];
            v2[2 * i] = t.x; v2[2 * i + 1] = t.y;
        }
    }
    if (tid < N_) bd_s[tid] = g_bdot[b * N_ + tid];
    __syncthreads();

    unsigned visA = (l == 0) ? 1u : 0u;
    unsigned visD = (l == 0) ? 1u : 0u;
    float lp = 0.f;

    float4 pv;
    if (w < 8) pv = Pb[0 * 256 + w * 32 + l];

    for (int step = 0; step < N_ - 1; step++) {
        if (w < 8) {
            int n0 = 4 * l;
            float a0 = (visA & 1u) ? NEGV : pv.x;
            float a1 = (visA & 2u) ? NEGV : pv.y;
            float a2 = (visA & 4u) ? NEGV : pv.z;
            float a3 = (visA & 8u) ? NEGV : pv.w;
            float m = fmaxf(fmaxf(a0, a1), fmaxf(a2, a3));
#pragma unroll
            for (int o = 16; o; o >>= 1) m = fmaxf(m, __shfl_xor_sync(0xffffffffu, m, o));
            a0 = expf(a0 - m); a1 = expf(a1 - m); a2 = expf(a2 - m); a3 = expf(a3 - m);
            float ssum = a0 + a1 + a2 + a3;
#pragma unroll
            for (int o = 16; o; o >>= 1) ssum += __shfl_xor_sync(0xffffffffu, ssum, o);
            float inv = 1.0f / ssum;
            float4 wv;
            wv.x = a0 * inv; wv.y = a1 * inv; wv.z = a2 * inv; wv.w = a3 * inv;
            *(float4*)&attn_s[w * 132 + n0 + 4 * (l >= 16)] = wv;
        }
        __syncthreads();

        {
            int d = tid >> 1, nh = tid & 1, hh = d >> 5;
            const ulonglong2* ap2 = (const ulonglong2*)(attn_s + hh * 132 + nh * 68);
            u64 acc2 = 0ULL;
#pragma unroll
            for (int i = 0; i < 16; i++) {
                ulonglong2 av = ap2[i];
                ffma2(acc2, av.x, v2[2 * i]);
                ffma2(acc2, av.y, v2[2 * i + 1]);
            }
            float2 ac = unpack2(acc2);
            float acc = ac.x + ac.y;
            acc += __shfl_xor_sync(0xffffffffu, acc, 1);
            if (!nh) ctx_s[d] = acc;
        }
        __syncthreads();

        {
            const ulonglong2* c2 = (const ulonglong2*)ctx_s + pL * 16;
            const ulonglong2* mr = (const ulonglong2*)Ms4T + (pL * 16) * MTU + nL;
            u64 sA = 0ULL, sB = 0ULL;
#pragma unroll
            for (int i = 0; i < MRC; i++) {
                ulonglong2 c = c2[i];
                ffma2(sA, Mreg2[2 * i], c.x);
                ffma2(sB, Mreg2[2 * i + 1], c.y);
            }
#pragma unroll
            for (int i = MRC; i < 16; i++) {
                ulonglong2 mv = mr[i * MTU];
                ulonglong2 c = c2[i];
                ffma2(sA, mv.x, c.x);
                ffma2(sB, mv.y, c.y);
            }
            float2 a = unpack2(sA), bq = unpack2(sB);
            lp_part[pL][nL] = (a.x + a.y) + (bq.x + bq.y);
        }
        __syncthreads();

        if (tid < N_) {
            float s = lp_part[0][tid] + lp_part[1][tid] + lp_part[2][tid] + lp_part[3][tid];
            float lg = tanhf(fmaf(SCALE_, s, bd_s[tid])) * CLIPV;
            if ((visD >> w) & 1u) lg = NEGV;
            logits_s[tid] = lg;
        }
        __syncthreads();

        if (w <= 8) {
            float lv[4];
            float bv = -3.0e38f; int bi = 0;
#pragma unroll
            for (int j = 0; j < 4; j++) {
                lv[j] = logits_s[l + 32 * j];
                if (lv[j] > bv) { bv = lv[j]; bi = l + 32 * j; }
            }
#pragma unroll
            for (int o = 16; o; o >>= 1) {
                float ov = __shfl_xor_sync(0xffffffffu, bv, o);
                int oi = __shfl_xor_sync(0xffffffffu, bi, o);
                if (ov > bv || (ov == bv && oi < bi)) { bv = ov; bi = oi; }
            }
            if ((bi >> 2) == l) visA |= 1u << (bi & 3);
            if ((bi & 31) == l) visD |= 1u << (bi >> 5);
            if (w < 8) pv = Pb[(size_t)bi * 256 + w * 32 + l];

            if (w == 8) {
                float es = 0.f;
#pragma unroll
                for (int j = 0; j < 4; j++) es += expf(lv[j] - bv);
#pragma unroll
                for (int o = 16; o; o >>= 1) es += __shfl_xor_sync(0xffffffffu, es, o);
                lp -= logf(es);
            }
        }
    }

    if (tid == 256) out[b] = lp;   // warp 8, lane 0
}

// ---------------- host launch ----------------
extern "C" void kernel_launch(void* const* d_in, const int* in_sizes, int n_in,
                              void* d_out, int out_size) {
    const float* ne    = (const float*)d_in[0];
    const float* Wqkv  = (const float*)d_in[1];
    const float* bqkv  = (const float*)d_in[2];
    const float* Wfix  = (const float*)d_in[3];
    const float* bfix  = (const float*)d_in[4];
    const float* Wstep = (const float*)d_in[5];
    const float* bstep = (const float*)d_in[6];
    const float* Wmlp  = (const float*)d_in[7];
    const float* bmlp  = (const float*)d_in[8];
    float* out = (float*)d_out;

    float *p_qkv = nullptr, *p_Qc = nullptr, *p_M = nullptr, *p_P = nullptr, *p_wt = nullptr;
    cudaGetSymbolAddress((void**)&p_qkv, g_qkv);
    cudaGetSymbolAddress((void**)&p_Qc, g_Qc);
    cudaGetSymbolAddress((void**)&p_M, g_M);
    cudaGetSymbolAddress((void**)&p_P, g_P);
    cudaGetSymbolAddress((void**)&p_wt, g_wt);

    size_t dec_smem = (size_t)64 * MTU * sizeof(float4);   // 132096
    cudaFuncSetAttribute(decode_k, cudaFuncAttributeMaxDynamicSharedMemorySize,
                         (int)dec_smem);
    size_t gemm_smem = 3 * 4096 * sizeof(float);           // 49152
    cudaFuncSetAttribute(sgemm_k, cudaFuncAttributeMaxDynamicSharedMemorySize,
                         (int)gemm_smem);

    mean_k<<<B_, E_>>>(ne);
    qfirst_k<<<B_, E_>>>(ne, Wfix, bfix, Wstep, bstep);
    wtrans_k<<<64, 256>>>(Wmlp);

    sgemm_k<<<dim3(768 / 128, (B_ * N_) / 128), 256, gemm_smem>>>(
        ne, Wqkv, bqkv, p_qkv, E_, E_, 768, 768);
    sgemm_k<<<dim3(E_ / 128, (B_ * N_) / 128), 256, gemm_smem>>>(
        ne, Wstep + 256 * 256, nullptr, p_Qc, E_, E_, E_, E_);
    sgemm_k<<<dim3(E_ / 128, (B_ * N_) / 128), 256, gemm_smem>>>(
        p_qkv + 512, p_wt, nullptr, p_M, E_, 768, E_, E_);
    pmat_k<<<B_ * H_, 256>>>(p_P);
    vtrans_k<<<B_ * 8, 256>>>();
    bdot_k<<<(B_ * N_) / 8, 256>>>(bmlp);

    decode_k<<<B_, 512, dec_smem>>>(out);
}

// round 15
// speedup vs baseline: 1.5882x; 1.0411x over previous
#include <cuda_runtime.h>
#include <math.h>

#define B_ 512
#define N_ 128
#define E_ 256
#define H_ 8
#define D_ 32
#define SCALE_ 0.17677669529663687f  /* 1/sqrt(32) */
#define NEGV  (-1000000000.0f)
#define CLIPV 10.0f
#define MTU   129                    /* Ms4T row stride in float4 units */
#define MRC   6                      /* M float4s cached in registers per thread */

typedef unsigned long long u64;

// packed fp32x2 FMA: d = a*b + d  (elementwise on (lo,hi))
__device__ __forceinline__ void ffma2(u64& d, u64 a, u64 b) {
    asm("fma.rn.f32x2 %0, %1, %2, %0;" : "+l"(d) : "l"(a), "l"(b));
}
__device__ __forceinline__ u64 pack2(float x, float y) {
    u64 r; asm("mov.b64 %0, {%1, %2};" : "=l"(r) : "f"(x), "f"(y)); return r;
}
__device__ __forceinline__ float2 unpack2(u64 v) {
    float2 r; asm("mov.b64 {%0, %1}, %2;" : "=f"(r.x), "=f"(r.y) : "l"(v)); return r;
}
__device__ __forceinline__ void cp_async16(unsigned smem_addr, const void* gptr) {
    asm volatile("cp.async.cg.shared.global [%0], [%1], 16;"
                 :: "r"(smem_addr), "l"(gptr));
}

// ---------------- scratch (device globals; no allocation) ----------------
__device__ float g_qkv[(size_t)B_ * N_ * 768];   // k | v | logit_k
__device__ float g_Qc [(size_t)B_ * N_ * E_];    // X @ Wstep_bot
__device__ float g_M  [(size_t)B_ * N_ * E_];    // logit_k @ Wmlp^T
__device__ float g_P  [(size_t)B_ * N_ * 1024];  // precomputed attn logits [b][i][h][n]
__device__ float g_vt [(size_t)B_ * E_ * N_];    // v transposed [b][d][n]
__device__ float g_wt [E_ * E_];                 // Wmlp^T
__device__ float g_bdot[B_ * N_];
__device__ float g_ge [B_ * E_];
__device__ float g_qf [B_ * E_];

// ---------------- graph_emb = mean over nodes ----------------
__global__ void mean_k(const float* __restrict__ ne) {
    int b = blockIdx.x, e = threadIdx.x;
    const float* p = ne + (size_t)b * N_ * E_ + e;
    float s = 0.f;
#pragma unroll 8
    for (int n = 0; n < N_; n++) s += p[(size_t)n * E_];
    g_ge[b * E_ + e] = s * (1.0f / N_);
}

// ---------------- q_first = ge@Wfix + first@Wstep_top + bfix + bstep ----------------
__global__ void qfirst_k(const float* __restrict__ ne,
                         const float* __restrict__ Wfix, const float* __restrict__ bfix,
                         const float* __restrict__ Wstep, const float* __restrict__ bstep) {
    __shared__ float ge_s[E_], fi_s[E_];
    int b = blockIdx.x, t = threadIdx.x;
    ge_s[t] = g_ge[b * E_ + t];
    fi_s[t] = ne[(size_t)b * N_ * E_ + t];
    __syncthreads();
    float acc = bfix[t] + bstep[t];
#pragma unroll 4
    for (int f = 0; f < E_; f++) {
        acc = fmaf(ge_s[f], Wfix[f * E_ + t], acc);
        acc = fmaf(fi_s[f], Wstep[f * E_ + t], acc);
    }
    g_qf[b * E_ + t] = acc;
}

// ---------------- Wmlp transpose: g_wt[j][i] = Wmlp[i][j] ----------------
__global__ void wtrans_k(const float* __restrict__ W) {
    __shared__ float t[32][33];
    int bx = blockIdx.x & 7, by = blockIdx.x >> 3;
    int x = threadIdx.x & 31, y = threadIdx.x >> 5;   // 256 thr: 32x8
#pragma unroll
    for (int r = 0; r < 32; r += 8)
        t[y + r][x] = W[(by * 32 + y + r) * E_ + bx * 32 + x];
    __syncthreads();
#pragma unroll
    for (int r = 0; r < 32; r += 8)
        g_wt[(bx * 32 + y + r) * E_ + by * 32 + x] = t[x][y + r];
}

// ---------------- fp32 GEMM: C = A(MxK)*B(KxN) [+bias] ----------------
// cp.async 3-slot ring, one __syncthreads per 16-K tile, FFMA2 core,
// capped at 128 regs for 2 CTAs/SM. As row-major [128][16], Bs [16][128].
__global__ void __launch_bounds__(256, 2) sgemm_k(
    const float* __restrict__ A, const float* __restrict__ Bm,
    const float* __restrict__ bias, float* __restrict__ C,
    int K, int lda, int ldb, int ldc) {
    extern __shared__ __align__(16) float sm[];      // 3 slots x (As 2048 + Bs 2048)
    int tid = threadIdx.x;
    int tx = tid & 15, ty = tid >> 4;
    int rowBase = blockIdx.y * 128;
    int colBase = blockIdx.x * 128;

    u64 acc2[8][4];
#pragma unroll
    for (int i = 0; i < 8; i++)
#pragma unroll
        for (int j = 0; j < 4; j++) acc2[i][j] = 0ULL;

    int arow = tid >> 2, ach = (tid & 3) * 4;        // A: 2 chunks (rows arow, arow+64)
    int bk = tid >> 5, bc = (tid & 31) * 4;          // B: 2 chunks (k-rows bk, bk+8)

    // precompute fixed pointers/offsets once (keeps per-tile addressing tiny)
    const char* Ag0 = (const char*)(A + (size_t)(rowBase + arow) * lda + ach);
    const char* Ag1 = (const char*)(A + (size_t)(rowBase + arow + 64) * lda + ach);
    const char* Bg0 = (const char*)(Bm + (size_t)bk * ldb + colBase + bc);
    const char* Bg1 = (const char*)(Bm + (size_t)(bk + 8) * ldb + colBase + bc);
    size_t bStep = (size_t)ldb * 16 * 4;             // bytes per 16-K tile for B
    unsigned sm_u = (unsigned)__cvta_generic_to_shared(sm);
    unsigned sA0 = sm_u + (arow * 16 + ach) * 4;
    unsigned sA1 = sm_u + ((arow + 64) * 16 + ach) * 4;
    unsigned sB0 = sm_u + 2048 * 4 + (bk * 128 + bc) * 4;
    unsigned sB1 = sm_u + 2048 * 4 + ((bk + 8) * 128 + bc) * 4;

    int T = K / 16;
    // prologue: tile 0 -> slot 0
    cp_async16(sA0, Ag0);
    cp_async16(sA1, Ag1);
    cp_async16(sB0, Bg0);
    cp_async16(sB1, Bg1);
    asm volatile("cp.async.commit_group;" ::: "memory");

    for (int t = 0; t < T; t++) {
        if (t + 1 < T) {
            unsigned so = ((t + 1) % 3) * 4096 * 4;
            size_t ao = (size_t)(t + 1) * 64;        // 16 floats = 64 bytes
            cp_async16(sA0 + so, Ag0 + ao);
            cp_async16(sA1 + so, Ag1 + ao);
            cp_async16(sB0 + so, Bg0 + (size_t)(t + 1) * bStep);
            cp_async16(sB1 + so, Bg1 + (size_t)(t + 1) * bStep);
            asm volatile("cp.async.commit_group;" ::: "memory");
            asm volatile("cp.async.wait_group 1;" ::: "memory");
        } else {
            asm volatile("cp.async.wait_group 0;" ::: "memory");
        }
        __syncthreads();

        const float* As = sm + (t % 3) * 4096;
        const float* Bs = As + 2048;
#pragma unroll
        for (int kk = 0; kk < 16; kk++) {
            u64 rb2[4];
            {
                ulonglong2 t0 = *(const ulonglong2*)&Bs[kk * 128 + tx * 8];
                ulonglong2 t1 = *(const ulonglong2*)&Bs[kk * 128 + tx * 8 + 4];
                rb2[0] = t0.x; rb2[1] = t0.y; rb2[2] = t1.x; rb2[3] = t1.y;
            }
#pragma unroll
            for (int i = 0; i < 8; i++) {
                float a = As[(ty * 8 + i) * 16 + kk];
                u64 raa = pack2(a, a);
#pragma unroll
                for (int j = 0; j < 4; j++) ffma2(acc2[i][j], raa, rb2[j]);
            }
        }
        // one barrier per tile: cp.async into slot (t+2)%3 is ordered after
        // every thread's compute on that slot (two syncs back).
    }
#pragma unroll
    for (int i = 0; i < 8; i++) {
        int r = rowBase + ty * 8 + i;
#pragma unroll
        for (int j = 0; j < 2; j++) {
            int c = colBase + tx * 8 + j * 4;
            float2 p0 = unpack2(acc2[i][2 * j + 0]);
            float2 p1 = unpack2(acc2[i][2 * j + 1]);
            float4 v;
            v.x = p0.x; v.y = p0.y; v.z = p1.x; v.w = p1.y;
            if (bias) { v.x += bias[c]; v.y += bias[c + 1]; v.z += bias[c + 2]; v.w += bias[c + 3]; }
            *(float4*)(C + (size_t)r * ldc + c) = v;
        }
    }
}

// ---------------- P[b][i][h][n] = SCALE * (qf[b]+Qc[b][i])_h . k[b][n]_h ----------------
__global__ void __launch_bounds__(256) pmat_k(float* __restrict__ P) {
    __shared__ __align__(16) float kt[32][132];
    __shared__ __align__(16) float qt[32][132];
    int h = blockIdx.x & 7, b = blockIdx.x >> 3;
    int tid = threadIdx.x;
    const float* kb  = g_qkv + (size_t)b * N_ * 768 + h * 32;
    const float* qcb = g_Qc  + (size_t)b * N_ * 256 + h * 32;
    const float* qfb = g_qf  + b * 256 + h * 32;

    for (int idx = tid; idx < N_ * 8; idx += 256) {
        int n = idx >> 3, d4 = (idx & 7) * 4;
        float4 kv  = *(const float4*)(kb  + (size_t)n * 768 + d4);
        float4 qv  = *(const float4*)(qcb + (size_t)n * 256 + d4);
        float4 qf4 = *(const float4*)(qfb + d4);
        kt[d4 + 0][n] = kv.x; kt[d4 + 1][n] = kv.y;
        kt[d4 + 2][n] = kv.z; kt[d4 + 3][n] = kv.w;
        qt[d4 + 0][n] = qv.x + qf4.x; qt[d4 + 1][n] = qv.y + qf4.y;
        qt[d4 + 2][n] = qv.z + qf4.z; qt[d4 + 3][n] = qv.w + qf4.w;
    }
    __syncthreads();

    int tx = tid & 15, ty = tid >> 4;
    u64 acc2[8][4];
#pragma unroll
    for (int i = 0; i < 8; i++)
#pragma unroll
        for (int j = 0; j < 4; j++) acc2[i][j] = 0ULL;

#pragma unroll 4
    for (int d = 0; d < 32; d++) {
        float ra[8];
        u64 rb2[4];
        *(float4*)&ra[0] = *(const float4*)&qt[d][ty * 8];
        *(float4*)&ra[4] = *(const float4*)&qt[d][ty * 8 + 4];
        {
            ulonglong2 t0 = *(const ulonglong2*)&kt[d][tx * 8];
            ulonglong2 t1 = *(const ulonglong2*)&kt[d][tx * 8 + 4];
            rb2[0] = t0.x; rb2[1] = t0.y; rb2[2] = t1.x; rb2[3] = t1.y;
        }
#pragma unroll
        for (int i = 0; i < 8; i++) {
            u64 raa = pack2(ra[i], ra[i]);
#pragma unroll
            for (int j = 0; j < 4; j++) ffma2(acc2[i][j], raa, rb2[j]);
        }
    }

#pragma unroll
    for (int i = 0; i < 8; i++) {
        float* row = P + ((size_t)(b * N_ + ty * 8 + i)) * 1024 + h * 128 + tx * 8;
#pragma unroll
        for (int j = 0; j < 2; j++) {
            float2 p0 = unpack2(acc2[i][2 * j + 0]);
            float2 p1 = unpack2(acc2[i][2 * j + 1]);
            float4 v;
            v.x = p0.x * SCALE_; v.y = p0.y * SCALE_;
            v.z = p1.x * SCALE_; v.w = p1.y * SCALE_;
            *(float4*)(row + j * 4) = v;
        }
    }
}

// ---------------- v transpose: g_vt[b][d][n] = qkv[b][n][256+d] ----------------
__global__ void __launch_bounds__(256) vtrans_k() {
    __shared__ float ts[32][33];
    int b = blockIdx.x >> 3, dt = blockIdx.x & 7;
    int tid = threadIdx.x;
    const float* src = g_qkv + (size_t)b * N_ * 768 + 256 + dt * 32;
    float* dst = g_vt + ((size_t)b * 256 + dt * 32) * 128;
    for (int nt = 0; nt < 4; nt++) {
        int nn = tid >> 3, dd4 = (tid & 7) * 4;
        float4 vv = *(const float4*)(src + (size_t)(nt * 32 + nn) * 768 + dd4);
        ts[dd4 + 0][nn] = vv.x; ts[dd4 + 1][nn] = vv.y;
        ts[dd4 + 2][nn] = vv.z; ts[dd4 + 3][nn] = vv.w;
        __syncthreads();
        int dd = tid >> 5, n2 = tid & 31;
#pragma unroll
        for (int r = 0; r < 4; r++)
            dst[(size_t)(dd + r * 8) * 128 + nt * 32 + n2] = ts[dd + r * 8][n2];
        __syncthreads();
    }
}

// ---------------- bdot[row] = SCALE * (bmlp . logit_k[row]) ----------------
__global__ void bdot_k(const float* __restrict__ bmlp) {
    int w = threadIdx.x >> 5, l = threadIdx.x & 31;
    int row = blockIdx.x * 8 + w;
    const float* lk = g_qkv + (size_t)row * 768 + 512;
    float acc = 0.f;
#pragma unroll
    for (int j = 0; j < 8; j++) acc = fmaf(bmlp[l + 32 * j], lk[l + 32 * j], acc);
#pragma unroll
    for (int o = 16; o; o >>= 1) acc += __shfl_xor_sync(0xffffffffu, acc, o);
    if (l == 0) g_bdot[row] = acc * SCALE_;
}

// ---------------- sequential greedy decode: 1 CTA (512 thr) per batch ----------------
// Unchanged from R13/R14 (MRC=6; phase E on warps 0-8; lse on warp 8).
__global__ void __launch_bounds__(512, 1) decode_k(float* __restrict__ out) {
    extern __shared__ __align__(16) float dyn_s[];
    float4* Ms4T = (float4*)dyn_s;                   // [64 u][MTU], n contiguous

    __shared__ __align__(16) float attn_s[H_ * 132]; // [h][n], +4 pad at n>=64
    __shared__ __align__(16) float ctx_s[E_];
    __shared__ float lp_part[4][N_];
    __shared__ float logits_s[N_];
    __shared__ float bd_s[N_];

    int b = blockIdx.x, tid = threadIdx.x;
    int w = tid >> 5, l = tid & 31;
    int nL = tid & 127, pL = tid >> 7;

    const float4* Mb4 = (const float4*)(g_M + (size_t)b * N_ * E_);
    const float4* Pb = (const float4*)(g_P + (size_t)b * N_ * 1024);

    for (int idx = tid; idx < N_ * 64; idx += 512) {
        int n = idx >> 6, u = idx & 63;
        Ms4T[u * MTU + n] = Mb4[n * 64 + u];
    }
    u64 Mreg2[2 * MRC];
#pragma unroll
    for (int i = 0; i < MRC; i++) {
        ulonglong2 t = *(const ulonglong2*)(Mb4 + nL * 64 + pL * 16 + i);
        Mreg2[2 * i] = t.x; Mreg2[2 * i + 1] = t.y;
    }
    u64 v2[32];
    {
        int d = tid >> 1, nh = tid & 1;
        const ulonglong2* vb2 = (const ulonglong2*)(g_vt + ((size_t)b * 256 + d) * 128 + nh * 64);
#pragma unroll
        for (int i = 0; i < 16; i++) {
            ulonglong2 t = vb2[i];
            v2[2 * i] = t.x; v2[2 * i + 1] = t.y;
        }
    }
    if (tid < N_) bd_s[tid] = g_bdot[b * N_ + tid];
    __syncthreads();

    unsigned visA = (l == 0) ? 1u : 0u;
    unsigned visD = (l == 0) ? 1u : 0u;
    float lp = 0.f;

    float4 pv;
    if (w < 8) pv = Pb[0 * 256 + w * 32 + l];

    for (int step = 0; step < N_ - 1; step++) {
        if (w < 8) {
            int n0 = 4 * l;
            float a0 = (visA & 1u) ? NEGV : pv.x;
            float a1 = (visA & 2u) ? NEGV : pv.y;
            float a2 = (visA & 4u) ? NEGV : pv.z;
            float a3 = (visA & 8u) ? NEGV : pv.w;
            float m = fmaxf(fmaxf(a0, a1), fmaxf(a2, a3));
#pragma unroll
            for (int o = 16; o; o >>= 1) m = fmaxf(m, __shfl_xor_sync(0xffffffffu, m, o));
            a0 = expf(a0 - m); a1 = expf(a1 - m); a2 = expf(a2 - m); a3 = expf(a3 - m);
            float ssum = a0 + a1 + a2 + a3;
#pragma unroll
            for (int o = 16; o; o >>= 1) ssum += __shfl_xor_sync(0xffffffffu, ssum, o);
            float inv = 1.0f / ssum;
            float4 wv;
            wv.x = a0 * inv; wv.y = a1 * inv; wv.z = a2 * inv; wv.w = a3 * inv;
            *(float4*)&attn_s[w * 132 + n0 + 4 * (l >= 16)] = wv;
        }
        __syncthreads();

        {
            int d = tid >> 1, nh = tid & 1, hh = d >> 5;
            const ulonglong2* ap2 = (const ulonglong2*)(attn_s + hh * 132 + nh * 68);
            u64 acc2 = 0ULL;
#pragma unroll
            for (int i = 0; i < 16; i++) {
                ulonglong2 av = ap2[i];
                ffma2(acc2, av.x, v2[2 * i]);
                ffma2(acc2, av.y, v2[2 * i + 1]);
            }
            float2 ac = unpack2(acc2);
            float acc = ac.x + ac.y;
            acc += __shfl_xor_sync(0xffffffffu, acc, 1);
            if (!nh) ctx_s[d] = acc;
        }
        __syncthreads();

        {
            const ulonglong2* c2 = (const ulonglong2*)ctx_s + pL * 16;
            const ulonglong2* mr = (const ulonglong2*)Ms4T + (pL * 16) * MTU + nL;
            u64 sA = 0ULL, sB = 0ULL;
#pragma unroll
            for (int i = 0; i < MRC; i++) {
                ulonglong2 c = c2[i];
                ffma2(sA, Mreg2[2 * i], c.x);
                ffma2(sB, Mreg2[2 * i + 1], c.y);
            }
#pragma unroll
            for (int i = MRC; i < 16; i++) {
                ulonglong2 mv = mr[i * MTU];
                ulonglong2 c = c2[i];
                ffma2(sA, mv.x, c.x);
                ffma2(sB, mv.y, c.y);
            }
            float2 a = unpack2(sA), bq = unpack2(sB);
            lp_part[pL][nL] = (a.x + a.y) + (bq.x + bq.y);
        }
        __syncthreads();

        if (tid < N_) {
            float s = lp_part[0][tid] + lp_part[1][tid] + lp_part[2][tid] + lp_part[3][tid];
            float lg = tanhf(fmaf(SCALE_, s, bd_s[tid])) * CLIPV;
            if ((visD >> w) & 1u) lg = NEGV;
            logits_s[tid] = lg;
        }
        __syncthreads();

        if (w <= 8) {
            float lv[4];
            float bv = -3.0e38f; int bi = 0;
#pragma unroll
            for (int j = 0; j < 4; j++) {
                lv[j] = logits_s[l + 32 * j];
                if (lv[j] > bv) { bv = lv[j]; bi = l + 32 * j; }
            }
#pragma unroll
            for (int o = 16; o; o >>= 1) {
                float ov = __shfl_xor_sync(0xffffffffu, bv, o);
                int oi = __shfl_xor_sync(0xffffffffu, bi, o);
                if (ov > bv || (ov == bv && oi < bi)) { bv = ov; bi = oi; }
            }
            if ((bi >> 2) == l) visA |= 1u << (bi & 3);
            if ((bi & 31) == l) visD |= 1u << (bi >> 5);
            if (w < 8) pv = Pb[(size_t)bi * 256 + w * 32 + l];

            if (w == 8) {
                float es = 0.f;
#pragma unroll
                for (int j = 0; j < 4; j++) es += expf(lv[j] - bv);
#pragma unroll
                for (int o = 16; o; o >>= 1) es += __shfl_xor_sync(0xffffffffu, es, o);
                lp -= logf(es);
            }
        }
    }

    if (tid == 256) out[b] = lp;   // warp 8, lane 0
}

// ---------------- host launch ----------------
extern "C" void kernel_launch(void* const* d_in, const int* in_sizes, int n_in,
                              void* d_out, int out_size) {
    const float* ne    = (const float*)d_in[0];
    const float* Wqkv  = (const float*)d_in[1];
    const float* bqkv  = (const float*)d_in[2];
    const float* Wfix  = (const float*)d_in[3];
    const float* bfix  = (const float*)d_in[4];
    const float* Wstep = (const float*)d_in[5];
    const float* bstep = (const float*)d_in[6];
    const float* Wmlp  = (const float*)d_in[7];
    const float* bmlp  = (const float*)d_in[8];
    float* out = (float*)d_out;

    float *p_qkv = nullptr, *p_Qc = nullptr, *p_M = nullptr, *p_P = nullptr, *p_wt = nullptr;
    cudaGetSymbolAddress((void**)&p_qkv, g_qkv);
    cudaGetSymbolAddress((void**)&p_Qc, g_Qc);
    cudaGetSymbolAddress((void**)&p_M, g_M);
    cudaGetSymbolAddress((void**)&p_P, g_P);
    cudaGetSymbolAddress((void**)&p_wt, g_wt);

    size_t dec_smem = (size_t)64 * MTU * sizeof(float4);   // 132096
    cudaFuncSetAttribute(decode_k, cudaFuncAttributeMaxDynamicSharedMemorySize,
                         (int)dec_smem);
    size_t gemm_smem = 3 * 4096 * sizeof(float);           // 49152
    cudaFuncSetAttribute(sgemm_k, cudaFuncAttributeMaxDynamicSharedMemorySize,
                         (int)gemm_smem);

    mean_k<<<B_, E_>>>(ne);
    qfirst_k<<<B_, E_>>>(ne, Wfix, bfix, Wstep, bstep);
    wtrans_k<<<64, 256>>>(Wmlp);

    sgemm_k<<<dim3(768 / 128, (B_ * N_) / 128), 256, gemm_smem>>>(
        ne, Wqkv, bqkv, p_qkv, E_, E_, 768, 768);
    sgemm_k<<<dim3(E_ / 128, (B_ * N_) / 128), 256, gemm_smem>>>(
        ne, Wstep + 256 * 256, nullptr, p_Qc, E_, E_, E_, E_);
    sgemm_k<<<dim3(E_ / 128, (B_ * N_) / 128), 256, gemm_smem>>>(
        p_qkv + 512, p_wt, nullptr, p_M, E_, 768, E_, E_);
    pmat_k<<<B_ * H_, 256>>>(p_P);
    vtrans_k<<<B_ * 8, 256>>>();
    bdot_k<<<(B_ * N_) / 8, 256>>>(bmlp);

    decode_k<<<B_, 512, dec_smem>>>(out);
}

// round 16
// speedup vs baseline: 1.6020x; 1.0087x over previous
#include <cuda_runtime.h>
#include <math.h>

#define B_ 512
#define N_ 128
#define E_ 256
#define H_ 8
#define D_ 32
#define SCALE_ 0.17677669529663687f  /* 1/sqrt(32) */
#define NEGV  (-1000000000.0f)
#define CLIPV 10.0f
#define MTU   129                    /* Ms4T row stride in float4 units */
#define MRC   6                      /* M float4s cached in registers per thread */

typedef unsigned long long u64;

// packed fp32x2 FMA: d = a*b + d  (elementwise on (lo,hi))
__device__ __forceinline__ void ffma2(u64& d, u64 a, u64 b) {
    asm("fma.rn.f32x2 %0, %1, %2, %0;" : "+l"(d) : "l"(a), "l"(b));
}
__device__ __forceinline__ u64 pack2(float x, float y) {
    u64 r; asm("mov.b64 %0, {%1, %2};" : "=l"(r) : "f"(x), "f"(y)); return r;
}
__device__ __forceinline__ float2 unpack2(u64 v) {
    float2 r; asm("mov.b64 {%0, %1}, %2;" : "=f"(r.x), "=f"(r.y) : "l"(v)); return r;
}
__device__ __forceinline__ void cp_async16(unsigned smem_addr, const void* gptr) {
    asm volatile("cp.async.cg.shared.global [%0], [%1], 16;"
                 :: "r"(smem_addr), "l"(gptr));
}

// ---------------- scratch (device globals; no allocation) ----------------
__device__ float g_qkv[(size_t)B_ * N_ * 768];   // k | v | logit_k
__device__ float g_Qc [(size_t)B_ * N_ * E_];    // X @ Wstep_bot
__device__ float g_M  [(size_t)B_ * N_ * E_];    // logit_k @ Wmlp^T
__device__ float g_P  [(size_t)B_ * N_ * 1024];  // precomputed attn logits [b][i][h][n]
__device__ float g_vt [(size_t)B_ * E_ * N_];    // v transposed [b][d][n]
__device__ float g_wt [E_ * E_];                 // Wmlp^T
__device__ float g_bdot[B_ * N_];
__device__ float g_ge [B_ * E_];
__device__ float g_qf [B_ * E_];

// ---------------- graph_emb = mean over nodes ----------------
__global__ void mean_k(const float* __restrict__ ne) {
    int b = blockIdx.x, e = threadIdx.x;
    const float* p = ne + (size_t)b * N_ * E_ + e;
    float s = 0.f;
#pragma unroll 8
    for (int n = 0; n < N_; n++) s += p[(size_t)n * E_];
    g_ge[b * E_ + e] = s * (1.0f / N_);
}

// ---------------- q_first = ge@Wfix + first@Wstep_top + bfix + bstep ----------------
__global__ void qfirst_k(const float* __restrict__ ne,
                         const float* __restrict__ Wfix, const float* __restrict__ bfix,
                         const float* __restrict__ Wstep, const float* __restrict__ bstep) {
    __shared__ float ge_s[E_], fi_s[E_];
    int b = blockIdx.x, t = threadIdx.x;
    ge_s[t] = g_ge[b * E_ + t];
    fi_s[t] = ne[(size_t)b * N_ * E_ + t];
    __syncthreads();
    float acc = bfix[t] + bstep[t];
#pragma unroll 4
    for (int f = 0; f < E_; f++) {
        acc = fmaf(ge_s[f], Wfix[f * E_ + t], acc);
        acc = fmaf(fi_s[f], Wstep[f * E_ + t], acc);
    }
    g_qf[b * E_ + t] = acc;
}

// ---------------- Wmlp transpose: g_wt[j][i] = Wmlp[i][j] ----------------
__global__ void wtrans_k(const float* __restrict__ W) {
    __shared__ float t[32][33];
    int bx = blockIdx.x & 7, by = blockIdx.x >> 3;
    int x = threadIdx.x & 31, y = threadIdx.x >> 5;   // 256 thr: 32x8
#pragma unroll
    for (int r = 0; r < 32; r += 8)
        t[y + r][x] = W[(by * 32 + y + r) * E_ + bx * 32 + x];
    __syncthreads();
#pragma unroll
    for (int r = 0; r < 32; r += 8)
        g_wt[(bx * 32 + y + r) * E_ + by * 32 + x] = t[x][y + r];
}

// ---------------- fp32 GEMM: C = A(MxK)*B(KxN) [+bias] ----------------
// cp.async 3-slot ring, one __syncthreads per 16-K tile, FFMA2 core,
// capped at 128 regs for 2 CTAs/SM. As row-major [128][16], Bs [16][128].
__global__ void __launch_bounds__(256, 2) sgemm_k(
    const float* __restrict__ A, const float* __restrict__ Bm,
    const float* __restrict__ bias, float* __restrict__ C,
    int K, int lda, int ldb, int ldc) {
    extern __shared__ __align__(16) float sm[];      // 3 slots x (As 2048 + Bs 2048)
    int tid = threadIdx.x;
    int tx = tid & 15, ty = tid >> 4;
    int rowBase = blockIdx.y * 128;
    int colBase = blockIdx.x * 128;

    u64 acc2[8][4];
#pragma unroll
    for (int i = 0; i < 8; i++)
#pragma unroll
        for (int j = 0; j < 4; j++) acc2[i][j] = 0ULL;

    int arow = tid >> 2, ach = (tid & 3) * 4;        // A: 2 chunks (rows arow, arow+64)
    int bk = tid >> 5, bc = (tid & 31) * 4;          // B: 2 chunks (k-rows bk, bk+8)

    const char* Ag0 = (const char*)(A + (size_t)(rowBase + arow) * lda + ach);
    const char* Ag1 = (const char*)(A + (size_t)(rowBase + arow + 64) * lda + ach);
    const char* Bg0 = (const char*)(Bm + (size_t)bk * ldb + colBase + bc);
    const char* Bg1 = (const char*)(Bm + (size_t)(bk + 8) * ldb + colBase + bc);
    size_t bStep = (size_t)ldb * 16 * 4;             // bytes per 16-K tile for B
    unsigned sm_u = (unsigned)__cvta_generic_to_shared(sm);
    unsigned sA0 = sm_u + (arow * 16 + ach) * 4;
    unsigned sA1 = sm_u + ((arow + 64) * 16 + ach) * 4;
    unsigned sB0 = sm_u + 2048 * 4 + (bk * 128 + bc) * 4;
    unsigned sB1 = sm_u + 2048 * 4 + ((bk + 8) * 128 + bc) * 4;

    int T = K / 16;
    cp_async16(sA0, Ag0);
    cp_async16(sA1, Ag1);
    cp_async16(sB0, Bg0);
    cp_async16(sB1, Bg1);
    asm volatile("cp.async.commit_group;" ::: "memory");

    for (int t = 0; t < T; t++) {
        if (t + 1 < T) {
            unsigned so = ((t + 1) % 3) * 4096 * 4;
            size_t ao = (size_t)(t + 1) * 64;        // 16 floats = 64 bytes
            cp_async16(sA0 + so, Ag0 + ao);
            cp_async16(sA1 + so, Ag1 + ao);
            cp_async16(sB0 + so, Bg0 + (size_t)(t + 1) * bStep);
            cp_async16(sB1 + so, Bg1 + (size_t)(t + 1) * bStep);
            asm volatile("cp.async.commit_group;" ::: "memory");
            asm volatile("cp.async.wait_group 1;" ::: "memory");
        } else {
            asm volatile("cp.async.wait_group 0;" ::: "memory");
        }
        __syncthreads();

        const float* As = sm + (t % 3) * 4096;
        const float* Bs = As + 2048;
#pragma unroll
        for (int kk = 0; kk < 16; kk++) {
            u64 rb2[4];
            {
                ulonglong2 t0 = *(const ulonglong2*)&Bs[kk * 128 + tx * 8];
                ulonglong2 t1 = *(const ulonglong2*)&Bs[kk * 128 + tx * 8 + 4];
                rb2[0] = t0.x; rb2[1] = t0.y; rb2[2] = t1.x; rb2[3] = t1.y;
            }
#pragma unroll
            for (int i = 0; i < 8; i++) {
                float a = As[(ty * 8 + i) * 16 + kk];
                u64 raa = pack2(a, a);
#pragma unroll
                for (int j = 0; j < 4; j++) ffma2(acc2[i][j], raa, rb2[j]);
            }
        }
    }
#pragma unroll
    for (int i = 0; i < 8; i++) {
        int r = rowBase + ty * 8 + i;
#pragma unroll
        for (int j = 0; j < 2; j++) {
            int c = colBase + tx * 8 + j * 4;
            float2 p0 = unpack2(acc2[i][2 * j + 0]);
            float2 p1 = unpack2(acc2[i][2 * j + 1]);
            float4 v;
            v.x = p0.x; v.y = p0.y; v.z = p1.x; v.w = p1.y;
            if (bias) { v.x += bias[c]; v.y += bias[c + 1]; v.z += bias[c + 2]; v.w += bias[c + 3]; }
            *(float4*)(C + (size_t)r * ldc + c) = v;
        }
    }
}

// ---------------- P[b][i][h][n] = SCALE * (qf[b]+Qc[b][i])_h . k[b][n]_h ----------------
__global__ void __launch_bounds__(256) pmat_k(float* __restrict__ P) {
    __shared__ __align__(16) float kt[32][132];
    __shared__ __align__(16) float qt[32][132];
    int h = blockIdx.x & 7, b = blockIdx.x >> 3;
    int tid = threadIdx.x;
    const float* kb  = g_qkv + (size_t)b * N_ * 768 + h * 32;
    const float* qcb = g_Qc  + (size_t)b * N_ * 256 + h * 32;
    const float* qfb = g_qf  + b * 256 + h * 32;

    for (int idx = tid; idx < N_ * 8; idx += 256) {
        int n = idx >> 3, d4 = (idx & 7) * 4;
        float4 kv  = *(const float4*)(kb  + (size_t)n * 768 + d4);
        float4 qv  = *(const float4*)(qcb + (size_t)n * 256 + d4);
        float4 qf4 = *(const float4*)(qfb + d4);
        kt[d4 + 0][n] = kv.x; kt[d4 + 1][n] = kv.y;
        kt[d4 + 2][n] = kv.z; kt[d4 + 3][n] = kv.w;
        qt[d4 + 0][n] = qv.x + qf4.x; qt[d4 + 1][n] = qv.y + qf4.y;
        qt[d4 + 2][n] = qv.z + qf4.z; qt[d4 + 3][n] = qv.w + qf4.w;
    }
    __syncthreads();

    int tx = tid & 15, ty = tid >> 4;
    u64 acc2[8][4];
#pragma unroll
    for (int i = 0; i < 8; i++)
#pragma unroll
        for (int j = 0; j < 4; j++) acc2[i][j] = 0ULL;

#pragma unroll 4
    for (int d = 0; d < 32; d++) {
        float ra[8];
        u64 rb2[4];
        *(float4*)&ra[0] = *(const float4*)&qt[d][ty * 8];
        *(float4*)&ra[4] = *(const float4*)&qt[d][ty * 8 + 4];
        {
            ulonglong2 t0 = *(const ulonglong2*)&kt[d][tx * 8];
            ulonglong2 t1 = *(const ulonglong2*)&kt[d][tx * 8 + 4];
            rb2[0] = t0.x; rb2[1] = t0.y; rb2[2] = t1.x; rb2[3] = t1.y;
        }
#pragma unroll
        for (int i = 0; i < 8; i++) {
            u64 raa = pack2(ra[i], ra[i]);
#pragma unroll
            for (int j = 0; j < 4; j++) ffma2(acc2[i][j], raa, rb2[j]);
        }
    }

#pragma unroll
    for (int i = 0; i < 8; i++) {
        float* row = P + ((size_t)(b * N_ + ty * 8 + i)) * 1024 + h * 128 + tx * 8;
#pragma unroll
        for (int j = 0; j < 2; j++) {
            float2 p0 = unpack2(acc2[i][2 * j + 0]);
            float2 p1 = unpack2(acc2[i][2 * j + 1]);
            float4 v;
            v.x = p0.x * SCALE_; v.y = p0.y * SCALE_;
            v.z = p1.x * SCALE_; v.w = p1.y * SCALE_;
            *(float4*)(row + j * 4) = v;
        }
    }
}

// ---------------- v transpose: g_vt[b][d][n] = qkv[b][n][256+d] ----------------
__global__ void __launch_bounds__(256) vtrans_k() {
    __shared__ float ts[32][33];
    int b = blockIdx.x >> 3, dt = blockIdx.x & 7;
    int tid = threadIdx.x;
    const float* src = g_qkv + (size_t)b * N_ * 768 + 256 + dt * 32;
    float* dst = g_vt + ((size_t)b * 256 + dt * 32) * 128;
    for (int nt = 0; nt < 4; nt++) {
        int nn = tid >> 3, dd4 = (tid & 7) * 4;
        float4 vv = *(const float4*)(src + (size_t)(nt * 32 + nn) * 768 + dd4);
        ts[dd4 + 0][nn] = vv.x; ts[dd4 + 1][nn] = vv.y;
        ts[dd4 + 2][nn] = vv.z; ts[dd4 + 3][nn] = vv.w;
        __syncthreads();
        int dd = tid >> 5, n2 = tid & 31;
#pragma unroll
        for (int r = 0; r < 4; r++)
            dst[(size_t)(dd + r * 8) * 128 + nt * 32 + n2] = ts[dd + r * 8][n2];
        __syncthreads();
    }
}

// ---------------- bdot[row] = SCALE * (bmlp . logit_k[row]) ----------------
__global__ void bdot_k(const float* __restrict__ bmlp) {
    int w = threadIdx.x >> 5, l = threadIdx.x & 31;
    int row = blockIdx.x * 8 + w;
    const float* lk = g_qkv + (size_t)row * 768 + 512;
    float acc = 0.f;
#pragma unroll
    for (int j = 0; j < 8; j++) acc = fmaf(bmlp[l + 32 * j], lk[l + 32 * j], acc);
#pragma unroll
    for (int o = 16; o; o >>= 1) acc += __shfl_xor_sync(0xffffffffu, acc, o);
    if (l == 0) g_bdot[row] = acc * SCALE_;
}

// ---------------- sequential greedy decode: 1 CTA (512 thr) per batch ----------------
// 3 barriers/step. tanh is OFF the critical path: argmax runs on raw
// pre-tanh logits (tanh monotone => same winner); warp 8 applies tanh only
// for the lse, hidden behind the next P-row DRAM load.
__global__ void __launch_bounds__(512, 1) decode_k(float* __restrict__ out) {
    extern __shared__ __align__(16) float dyn_s[];
    float4* Ms4T = (float4*)dyn_s;                   // [64 u][MTU], n contiguous

    __shared__ __align__(16) float attn_s[H_ * 132]; // [h][n], +4 pad at n>=64
    __shared__ __align__(16) float ctx_s[E_];
    __shared__ float lp_part[4][N_];

    int b = blockIdx.x, tid = threadIdx.x;
    int w = tid >> 5, l = tid & 31;
    int nL = tid & 127, pL = tid >> 7;

    const float4* Mb4 = (const float4*)(g_M + (size_t)b * N_ * E_);
    const float4* Pb = (const float4*)(g_P + (size_t)b * N_ * 1024);

    for (int idx = tid; idx < N_ * 64; idx += 512) {
        int n = idx >> 6, u = idx & 63;
        Ms4T[u * MTU + n] = Mb4[n * 64 + u];
    }
    u64 Mreg2[2 * MRC];
#pragma unroll
    for (int i = 0; i < MRC; i++) {
        ulonglong2 t = *(const ulonglong2*)(Mb4 + nL * 64 + pL * 16 + i);
        Mreg2[2 * i] = t.x; Mreg2[2 * i + 1] = t.y;
    }
    u64 v2[32];
    {
        int d = tid >> 1, nh = tid & 1;
        const ulonglong2* vb2 = (const ulonglong2*)(g_vt + ((size_t)b * 256 + d) * 128 + nh * 64);
#pragma unroll
        for (int i = 0; i < 16; i++) {
            ulonglong2 t = vb2[i];
            v2[2 * i] = t.x; v2[2 * i + 1] = t.y;
        }
    }
    // bd in registers: lane l of warps 0-8 holds bd[l + 32j], j=0..3
    float bd_r[4];
#pragma unroll
    for (int j = 0; j < 4; j++) bd_r[j] = g_bdot[b * N_ + l + 32 * j];
    __syncthreads();

    unsigned visA = (l == 0) ? 1u : 0u;              // bits 0..3 for n = 4l..4l+3
    unsigned visD = (l == 0) ? 1u : 0u;              // bit j for n = l + 32j
    float lp = 0.f;                                  // meaningful on warp 8 only

    float4 pv;
    if (w < 8) pv = Pb[0 * 256 + w * 32 + l];

    for (int step = 0; step < N_ - 1; step++) {
        // ---- A: warps 0..7 = heads; lane l owns n = 4l..4l+3 ----
        if (w < 8) {
            int n0 = 4 * l;
            float a0 = (visA & 1u) ? NEGV : pv.x;
            float a1 = (visA & 2u) ? NEGV : pv.y;
            float a2 = (visA & 4u) ? NEGV : pv.z;
            float a3 = (visA & 8u) ? NEGV : pv.w;
            float m = fmaxf(fmaxf(a0, a1), fmaxf(a2, a3));
#pragma unroll
            for (int o = 16; o; o >>= 1) m = fmaxf(m, __shfl_xor_sync(0xffffffffu, m, o));
            a0 = expf(a0 - m); a1 = expf(a1 - m); a2 = expf(a2 - m); a3 = expf(a3 - m);
            float ssum = a0 + a1 + a2 + a3;
#pragma unroll
            for (int o = 16; o; o >>= 1) ssum += __shfl_xor_sync(0xffffffffu, ssum, o);
            float inv = 1.0f / ssum;
            float4 wv;
            wv.x = a0 * inv; wv.y = a1 * inv; wv.z = a2 * inv; wv.w = a3 * inv;
            *(float4*)&attn_s[w * 132 + n0 + 4 * (l >= 16)] = wv;
        }
        __syncthreads();

        // ---- B: ctx[d] = sum_n attn[h(d)][n] * v[n][d]  (packed FFMA2) ----
        {
            int d = tid >> 1, nh = tid & 1, hh = d >> 5;
            const ulonglong2* ap2 = (const ulonglong2*)(attn_s + hh * 132 + nh * 68);
            u64 acc2 = 0ULL;
#pragma unroll
            for (int i = 0; i < 16; i++) {
                ulonglong2 av = ap2[i];
                ffma2(acc2, av.x, v2[2 * i]);
                ffma2(acc2, av.y, v2[2 * i + 1]);
            }
            float2 ac = unpack2(acc2);
            float acc = ac.x + ac.y;
            acc += __shfl_xor_sync(0xffffffffu, acc, 1);
            if (!nh) ctx_s[d] = acc;
        }
        __syncthreads();

        // ---- C: logits partials (packed FFMA2; first MRC float4 from regs) ----
        {
            const ulonglong2* c2 = (const ulonglong2*)ctx_s + pL * 16;
            const ulonglong2* mr = (const ulonglong2*)Ms4T + (pL * 16) * MTU + nL;
            u64 sA = 0ULL, sB = 0ULL;
#pragma unroll
            for (int i = 0; i < MRC; i++) {
                ulonglong2 c = c2[i];
                ffma2(sA, Mreg2[2 * i], c.x);
                ffma2(sB, Mreg2[2 * i + 1], c.y);
            }
#pragma unroll
            for (int i = MRC; i < 16; i++) {
                ulonglong2 mv = mr[i * MTU];
                ulonglong2 c = c2[i];
                ffma2(sA, mv.x, c.x);
                ffma2(sB, mv.y, c.y);
            }
            float2 a = unpack2(sA), bq = unpack2(sB);
            lp_part[pL][nL] = (a.x + a.y) + (bq.x + bq.y);
        }
        __syncthreads();

        // ---- E: warps 0-8: raw logits from lp_part, argmax on PRE-tanh values,
        //         state update, issue next P load; warp 8 tanh+lse behind it. ----
        if (w <= 8) {
            float r[4];
            float bv = -3.0e38f; int bi = 0;
#pragma unroll
            for (int j = 0; j < 4; j++) {
                int n = l + 32 * j;
                float s = lp_part[0][n] + lp_part[1][n] + lp_part[2][n] + lp_part[3][n];
                float rr = fmaf(SCALE_, s, bd_r[j]);
                if ((visD >> j) & 1u) rr = NEGV;
                r[j] = rr;
                if (rr > bv) { bv = rr; bi = n; }
            }
#pragma unroll
            for (int o = 16; o; o >>= 1) {
                float ov = __shfl_xor_sync(0xffffffffu, bv, o);
                int oi = __shfl_xor_sync(0xffffffffu, bi, o);
                if (ov > bv || (ov == bv && oi < bi)) { bv = ov; bi = oi; }
            }
            // state update + immediately issue next P row load
            if ((bi >> 2) == l) visA |= 1u << (bi & 3);
            if ((bi & 31) == l) visD |= 1u << (bi >> 5);
            if (w < 8) pv = Pb[(size_t)bi * 256 + w * 32 + l];

            // warp 8: tanh only here (off the critical path), then lse + logp
            if (w == 8) {
                float bvt = tanhf(bv) * CLIPV;       // bv is always unmasked
                float es = 0.f;
#pragma unroll
                for (int j = 0; j < 4; j++) {
                    float lvt = (r[j] == NEGV) ? NEGV : tanhf(r[j]) * CLIPV;
                    es += expf(lvt - bvt);
                }
#pragma unroll
                for (int o = 16; o; o >>= 1) es += __shfl_xor_sync(0xffffffffu, es, o);
                lp -= logf(es);
            }
        }
        // no trailing barrier: bar1..bar3 of the next step order all smem reuse
    }

    if (tid == 256) out[b] = lp;   // warp 8, lane 0
}

// ---------------- host launch ----------------
extern "C" void kernel_launch(void* const* d_in, const int* in_sizes, int n_in,
                              void* d_out, int out_size) {
    const float* ne    = (const float*)d_in[0];
    const float* Wqkv  = (const float*)d_in[1];
    const float* bqkv  = (const float*)d_in[2];
    const float* Wfix  = (const float*)d_in[3];
    const float* bfix  = (const float*)d_in[4];
    const float* Wstep = (const float*)d_in[5];
    const float* bstep = (const float*)d_in[6];
    const float* Wmlp  = (const float*)d_in[7];
    const float* bmlp  = (const float*)d_in[8];
    float* out = (float*)d_out;

    float *p_qkv = nullptr, *p_Qc = nullptr, *p_M = nullptr, *p_P = nullptr, *p_wt = nullptr;
    cudaGetSymbolAddress((void**)&p_qkv, g_qkv);
    cudaGetSymbolAddress((void**)&p_Qc, g_Qc);
    cudaGetSymbolAddress((void**)&p_M, g_M);
    cudaGetSymbolAddress((void**)&p_P, g_P);
    cudaGetSymbolAddress((void**)&p_wt, g_wt);

    size_t dec_smem = (size_t)64 * MTU * sizeof(float4);   // 132096
    cudaFuncSetAttribute(decode_k, cudaFuncAttributeMaxDynamicSharedMemorySize,
                         (int)dec_smem);
    size_t gemm_smem = 3 * 4096 * sizeof(float);           // 49152
    cudaFuncSetAttribute(sgemm_k, cudaFuncAttributeMaxDynamicSharedMemorySize,
                         (int)gemm_smem);

    mean_k<<<B_, E_>>>(ne);
    qfirst_k<<<B_, E_>>>(ne, Wfix, bfix, Wstep, bstep);
    wtrans_k<<<64, 256>>>(Wmlp);

    sgemm_k<<<dim3(768 / 128, (B_ * N_) / 128), 256, gemm_smem>>>(
        ne, Wqkv, bqkv, p_qkv, E_, E_, 768, 768);
    sgemm_k<<<dim3(E_ / 128, (B_ * N_) / 128), 256, gemm_smem>>>(
        ne, Wstep + 256 * 256, nullptr, p_Qc, E_, E_, E_, E_);
    sgemm_k<<<dim3(E_ / 128, (B_ * N_) / 128), 256, gemm_smem>>>(
        p_qkv + 512, p_wt, nullptr, p_M, E_, 768, E_, E_);
    pmat_k<<<B_ * H_, 256>>>(p_P);
    vtrans_k<<<B_ * 8, 256>>>();
    bdot_k<<<(B_ * N_) / 8, 256>>>(bmlp);

    decode_k<<<B_, 512, dec_smem>>>(out);
}

// round 17
// speedup vs baseline: 1.6150x; 1.0081x over previous
#include <cuda_runtime.h>
#include <math.h>

#define B_ 512
#define N_ 128
#define E_ 256
#define H_ 8
#define D_ 32
#define SCALE_ 0.17677669529663687f  /* 1/sqrt(32) */
#define NEGV  (-1000000000.0f)
#define CLIPV 10.0f
#define MTU   129                    /* Ms4T row stride in float4 units */
#define MRC   6                      /* M float4s cached in registers per thread */

typedef unsigned long long u64;

// packed fp32x2 FMA: d = a*b + d  (elementwise on (lo,hi))
__device__ __forceinline__ void ffma2(u64& d, u64 a, u64 b) {
    asm("fma.rn.f32x2 %0, %1, %2, %0;" : "+l"(d) : "l"(a), "l"(b));
}
__device__ __forceinline__ u64 pack2(float x, float y) {
    u64 r; asm("mov.b64 %0, {%1, %2};" : "=l"(r) : "f"(x), "f"(y)); return r;
}
__device__ __forceinline__ float2 unpack2(u64 v) {
    float2 r; asm("mov.b64 {%0, %1}, %2;" : "=f"(r.x), "=f"(r.y) : "l"(v)); return r;
}
__device__ __forceinline__ void cp_async16(unsigned smem_addr, const void* gptr) {
    asm volatile("cp.async.cg.shared.global [%0], [%1], 16;"
                 :: "r"(smem_addr), "l"(gptr));
}

// ---------------- scratch (device globals; no allocation) ----------------
__device__ float g_qkv[(size_t)B_ * N_ * 768];   // k | v | logit_k
__device__ float g_Qc [(size_t)B_ * N_ * E_];    // X @ Wstep_bot
__device__ float g_M  [(size_t)B_ * N_ * E_];    // logit_k @ Wmlp^T
__device__ float g_P  [(size_t)B_ * N_ * 1024];  // precomputed attn logits [b][i][h][n]
__device__ float g_vt [(size_t)B_ * E_ * N_];    // v transposed [b][d][n]
__device__ float g_wt [E_ * E_];                 // Wmlp^T
__device__ float g_bdot[B_ * N_];
__device__ float g_ge [B_ * E_];
__device__ float g_qf [B_ * E_];

// ---------------- graph_emb = mean over nodes ----------------
__global__ void mean_k(const float* __restrict__ ne) {
    int b = blockIdx.x, e = threadIdx.x;
    const float* p = ne + (size_t)b * N_ * E_ + e;
    float s = 0.f;
#pragma unroll 8
    for (int n = 0; n < N_; n++) s += p[(size_t)n * E_];
    g_ge[b * E_ + e] = s * (1.0f / N_);
}

// ---------------- q_first = ge@Wfix + first@Wstep_top + bfix + bstep ----------------
__global__ void qfirst_k(const float* __restrict__ ne,
                         const float* __restrict__ Wfix, const float* __restrict__ bfix,
                         const float* __restrict__ Wstep, const float* __restrict__ bstep) {
    __shared__ float ge_s[E_], fi_s[E_];
    int b = blockIdx.x, t = threadIdx.x;
    ge_s[t] = g_ge[b * E_ + t];
    fi_s[t] = ne[(size_t)b * N_ * E_ + t];
    __syncthreads();
    float acc = bfix[t] + bstep[t];
#pragma unroll 4
    for (int f = 0; f < E_; f++) {
        acc = fmaf(ge_s[f], Wfix[f * E_ + t], acc);
        acc = fmaf(fi_s[f], Wstep[f * E_ + t], acc);
    }
    g_qf[b * E_ + t] = acc;
}

// ---------------- Wmlp transpose: g_wt[j][i] = Wmlp[i][j] ----------------
__global__ void wtrans_k(const float* __restrict__ W) {
    __shared__ float t[32][33];
    int bx = blockIdx.x & 7, by = blockIdx.x >> 3;
    int x = threadIdx.x & 31, y = threadIdx.x >> 5;   // 256 thr: 32x8
#pragma unroll
    for (int r = 0; r < 32; r += 8)
        t[y + r][x] = W[(by * 32 + y + r) * E_ + bx * 32 + x];
    __syncthreads();
#pragma unroll
    for (int r = 0; r < 32; r += 8)
        g_wt[(bx * 32 + y + r) * E_ + by * 32 + x] = t[x][y + r];
}

// ---------------- fp32 GEMM: C = A(MxK)*B(KxN) [+bias] ----------------
// cp.async 4-slot ring, depth-2 prefetch, one __syncthreads per 16-K tile,
// FFMA2 core, capped at 128 regs for 2 CTAs/SM.
// As row-major [128][16], Bs [16][128]. K % 16 == 0.
__global__ void __launch_bounds__(256, 2) sgemm_k(
    const float* __restrict__ A, const float* __restrict__ Bm,
    const float* __restrict__ bias, float* __restrict__ C,
    int K, int lda, int ldb, int ldc) {
    extern __shared__ __align__(16) float sm[];      // 4 slots x (As 2048 + Bs 2048)
    int tid = threadIdx.x;
    int tx = tid & 15, ty = tid >> 4;
    int rowBase = blockIdx.y * 128;
    int colBase = blockIdx.x * 128;

    u64 acc2[8][4];
#pragma unroll
    for (int i = 0; i < 8; i++)
#pragma unroll
        for (int j = 0; j < 4; j++) acc2[i][j] = 0ULL;

    int arow = tid >> 2, ach = (tid & 3) * 4;        // A: 2 chunks (rows arow, arow+64)
    int bk = tid >> 5, bc = (tid & 31) * 4;          // B: 2 chunks (k-rows bk, bk+8)

    const char* Ag0 = (const char*)(A + (size_t)(rowBase + arow) * lda + ach);
    const char* Ag1 = (const char*)(A + (size_t)(rowBase + arow + 64) * lda + ach);
    const char* Bg0 = (const char*)(Bm + (size_t)bk * ldb + colBase + bc);
    const char* Bg1 = (const char*)(Bm + (size_t)(bk + 8) * ldb + colBase + bc);
    size_t bStep = (size_t)ldb * 16 * 4;             // bytes per 16-K tile for B
    unsigned sm_u = (unsigned)__cvta_generic_to_shared(sm);
    unsigned sA0 = sm_u + (arow * 16 + ach) * 4;
    unsigned sA1 = sm_u + ((arow + 64) * 16 + ach) * 4;
    unsigned sB0 = sm_u + 2048 * 4 + (bk * 128 + bc) * 4;
    unsigned sB1 = sm_u + 2048 * 4 + ((bk + 8) * 128 + bc) * 4;

    int T = K / 16;
    // prologue: tiles 0 and 1
    cp_async16(sA0, Ag0);
    cp_async16(sA1, Ag1);
    cp_async16(sB0, Bg0);
    cp_async16(sB1, Bg1);
    asm volatile("cp.async.commit_group;" ::: "memory");
    if (T > 1) {
        unsigned so = (1 % 4) * 4096 * 4;
        cp_async16(sA0 + so, Ag0 + 64);
        cp_async16(sA1 + so, Ag1 + 64);
        cp_async16(sB0 + so, Bg0 + bStep);
        cp_async16(sB1 + so, Bg1 + bStep);
        asm volatile("cp.async.commit_group;" ::: "memory");
    }

    for (int t = 0; t < T; t++) {
        if (t + 2 < T) {
            unsigned so = ((t + 2) & 3) * 4096 * 4;
            size_t ao = (size_t)(t + 2) * 64;        // 16 floats = 64 bytes
            cp_async16(sA0 + so, Ag0 + ao);
            cp_async16(sA1 + so, Ag1 + ao);
            cp_async16(sB0 + so, Bg0 + (size_t)(t + 2) * bStep);
            cp_async16(sB1 + so, Bg1 + (size_t)(t + 2) * bStep);
            asm volatile("cp.async.commit_group;" ::: "memory");
            asm volatile("cp.async.wait_group 2;" ::: "memory");
        } else if (t + 1 < T) {
            asm volatile("cp.async.wait_group 1;" ::: "memory");
        } else {
            asm volatile("cp.async.wait_group 0;" ::: "memory");
        }
        __syncthreads();

        const float* As = sm + (t & 3) * 4096;
        const float* Bs = As + 2048;
#pragma unroll
        for (int kk = 0; kk < 16; kk++) {
            u64 rb2[4];
            {
                ulonglong2 t0 = *(const ulonglong2*)&Bs[kk * 128 + tx * 8];
                ulonglong2 t1 = *(const ulonglong2*)&Bs[kk * 128 + tx * 8 + 4];
                rb2[0] = t0.x; rb2[1] = t0.y; rb2[2] = t1.x; rb2[3] = t1.y;
            }
#pragma unroll
            for (int i = 0; i < 8; i++) {
                float a = As[(ty * 8 + i) * 16 + kk];
                u64 raa = pack2(a, a);
#pragma unroll
                for (int j = 0; j < 4; j++) ffma2(acc2[i][j], raa, rb2[j]);
            }
        }
        // slot reuse safety: cp.async at iter t targets slot (t+2)&3; the most
        // recent readers of that slot were at iter t-2, separated by 2 barriers.
    }
#pragma unroll
    for (int i = 0; i < 8; i++) {
        int r = rowBase + ty * 8 + i;
#pragma unroll
        for (int j = 0; j < 2; j++) {
            int c = colBase + tx * 8 + j * 4;
            float2 p0 = unpack2(acc2[i][2 * j + 0]);
            float2 p1 = unpack2(acc2[i][2 * j + 1]);
            float4 v;
            v.x = p0.x; v.y = p0.y; v.z = p1.x; v.w = p1.y;
            if (bias) { v.x += bias[c]; v.y += bias[c + 1]; v.z += bias[c + 2]; v.w += bias[c + 3]; }
            *(float4*)(C + (size_t)r * ldc + c) = v;
        }
    }
}

// ---------------- P[b][i][h][n] = SCALE * (qf[b]+Qc[b][i])_h . k[b][n]_h ----------------
__global__ void __launch_bounds__(256) pmat_k(float* __restrict__ P) {
    __shared__ __align__(16) float kt[32][132];
    __shared__ __align__(16) float qt[32][132];
    int h = blockIdx.x & 7, b = blockIdx.x >> 3;
    int tid = threadIdx.x;
    const float* kb  = g_qkv + (size_t)b * N_ * 768 + h * 32;
    const float* qcb = g_Qc  + (size_t)b * N_ * 256 + h * 32;
    const float* qfb = g_qf  + b * 256 + h * 32;

    for (int idx = tid; idx < N_ * 8; idx += 256) {
        int n = idx >> 3, d4 = (idx & 7) * 4;
        float4 kv  = *(const float4*)(kb  + (size_t)n * 768 + d4);
        float4 qv  = *(const float4*)(qcb + (size_t)n * 256 + d4);
        float4 qf4 = *(const float4*)(qfb + d4);
        kt[d4 + 0][n] = kv.x; kt[d4 + 1][n] = kv.y;
        kt[d4 + 2][n] = kv.z; kt[d4 + 3][n] = kv.w;
        qt[d4 + 0][n] = qv.x + qf4.x; qt[d4 + 1][n] = qv.y + qf4.y;
        qt[d4 + 2][n] = qv.z + qf4.z; qt[d4 + 3][n] = qv.w + qf4.w;
    }
    __syncthreads();

    int tx = tid & 15, ty = tid >> 4;
    u64 acc2[8][4];
#pragma unroll
    for (int i = 0; i < 8; i++)
#pragma unroll
        for (int j = 0; j < 4; j++) acc2[i][j] = 0ULL;

#pragma unroll 4
    for (int d = 0; d < 32; d++) {
        float ra[8];
        u64 rb2[4];
        *(float4*)&ra[0] = *(const float4*)&qt[d][ty * 8];
        *(float4*)&ra[4] = *(const float4*)&qt[d][ty * 8 + 4];
        {
            ulonglong2 t0 = *(const ulonglong2*)&kt[d][tx * 8];
            ulonglong2 t1 = *(const ulonglong2*)&kt[d][tx * 8 + 4];
            rb2[0] = t0.x; rb2[1] = t0.y; rb2[2] = t1.x; rb2[3] = t1.y;
        }
#pragma unroll
        for (int i = 0; i < 8; i++) {
            u64 raa = pack2(ra[i], ra[i]);
#pragma unroll
            for (int j = 0; j < 4; j++) ffma2(acc2[i][j], raa, rb2[j]);
        }
    }

#pragma unroll
    for (int i = 0; i < 8; i++) {
        float* row = P + ((size_t)(b * N_ + ty * 8 + i)) * 1024 + h * 128 + tx * 8;
#pragma unroll
        for (int j = 0; j < 2; j++) {
            float2 p0 = unpack2(acc2[i][2 * j + 0]);
            float2 p1 = unpack2(acc2[i][2 * j + 1]);
            float4 v;
            v.x = p0.x * SCALE_; v.y = p0.y * SCALE_;
            v.z = p1.x * SCALE_; v.w = p1.y * SCALE_;
            *(float4*)(row + j * 4) = v;
        }
    }
}

// ---------------- v transpose: g_vt[b][d][n] = qkv[b][n][256+d] ----------------
__global__ void __launch_bounds__(256) vtrans_k() {
    __shared__ float ts[32][33];
    int b = blockIdx.x >> 3, dt = blockIdx.x & 7;
    int tid = threadIdx.x;
    const float* src = g_qkv + (size_t)b * N_ * 768 + 256 + dt * 32;
    float* dst = g_vt + ((size_t)b * 256 + dt * 32) * 128;
    for (int nt = 0; nt < 4; nt++) {
        int nn = tid >> 3, dd4 = (tid & 7) * 4;
        float4 vv = *(const float4*)(src + (size_t)(nt * 32 + nn) * 768 + dd4);
        ts[dd4 + 0][nn] = vv.x; ts[dd4 + 1][nn] = vv.y;
        ts[dd4 + 2][nn] = vv.z; ts[dd4 + 3][nn] = vv.w;
        __syncthreads();
        int dd = tid >> 5, n2 = tid & 31;
#pragma unroll
        for (int r = 0; r < 4; r++)
            dst[(size_t)(dd + r * 8) * 128 + nt * 32 + n2] = ts[dd + r * 8][n2];
        __syncthreads();
    }
}

// ---------------- bdot[row] = SCALE * (bmlp . logit_k[row]) ----------------
__global__ void bdot_k(const float* __restrict__ bmlp) {
    int w = threadIdx.x >> 5, l = threadIdx.x & 31;
    int row = blockIdx.x * 8 + w;
    const float* lk = g_qkv + (size_t)row * 768 + 512;
    float acc = 0.f;
#pragma unroll
    for (int j = 0; j < 8; j++) acc = fmaf(bmlp[l + 32 * j], lk[l + 32 * j], acc);
#pragma unroll
    for (int o = 16; o; o >>= 1) acc += __shfl_xor_sync(0xffffffffu, acc, o);
    if (l == 0) g_bdot[row] = acc * SCALE_;
}

// ---------------- sequential greedy decode: 1 CTA (512 thr) per batch ----------------
// 3 barriers/step. argmax on raw pre-tanh logits (tanh monotone); warp 8
// applies tanh only for the lse, hidden behind the next P-row DRAM load.
// lp_part stored [n][q] so E reads one LDS.128 per j; argmax reduce uses a
// packed u64 key (order-preserving float map | inverted index).
__global__ void __launch_bounds__(512, 1) decode_k(float* __restrict__ out) {
    extern __shared__ __align__(16) float dyn_s[];
    float4* Ms4T = (float4*)dyn_s;                   // [64 u][MTU], n contiguous

    __shared__ __align__(16) float attn_s[H_ * 132]; // [h][n], +4 pad at n>=64
    __shared__ __align__(16) float ctx_s[E_];
    __shared__ __align__(16) float lp_part[N_][4];   // [n][q]

    int b = blockIdx.x, tid = threadIdx.x;
    int w = tid >> 5, l = tid & 31;
    int nL = tid & 127, pL = tid >> 7;

    const float4* Mb4 = (const float4*)(g_M + (size_t)b * N_ * E_);
    const float4* Pb = (const float4*)(g_P + (size_t)b * N_ * 1024);

    for (int idx = tid; idx < N_ * 64; idx += 512) {
        int n = idx >> 6, u = idx & 63;
        Ms4T[u * MTU + n] = Mb4[n * 64 + u];
    }
    u64 Mreg2[2 * MRC];
#pragma unroll
    for (int i = 0; i < MRC; i++) {
        ulonglong2 t = *(const ulonglong2*)(Mb4 + nL * 64 + pL * 16 + i);
        Mreg2[2 * i] = t.x; Mreg2[2 * i + 1] = t.y;
    }
    u64 v2[32];
    {
        int d = tid >> 1, nh = tid & 1;
        const ulonglong2* vb2 = (const ulonglong2*)(g_vt + ((size_t)b * 256 + d) * 128 + nh * 64);
#pragma unroll
        for (int i = 0; i < 16; i++) {
            ulonglong2 t = vb2[i];
            v2[2 * i] = t.x; v2[2 * i + 1] = t.y;
        }
    }
    // bd in registers: lane l of warps 0-8 holds bd[l + 32j], j=0..3
    float bd_r[4];
#pragma unroll
    for (int j = 0; j < 4; j++) bd_r[j] = g_bdot[b * N_ + l + 32 * j];
    __syncthreads();

    unsigned visA = (l == 0) ? 1u : 0u;              // bits 0..3 for n = 4l..4l+3
    unsigned visD = (l == 0) ? 1u : 0u;              // bit j for n = l + 32j
    float lp = 0.f;                                  // meaningful on warp 8 only

    float4 pv;
    if (w < 8) pv = Pb[0 * 256 + w * 32 + l];

    for (int step = 0; step < N_ - 1; step++) {
        // ---- A: warps 0..7 = heads; lane l owns n = 4l..4l+3 ----
        if (w < 8) {
            int n0 = 4 * l;
            float a0 = (visA & 1u) ? NEGV : pv.x;
            float a1 = (visA & 2u) ? NEGV : pv.y;
            float a2 = (visA & 4u) ? NEGV : pv.z;
            float a3 = (visA & 8u) ? NEGV : pv.w;
            float m = fmaxf(fmaxf(a0, a1), fmaxf(a2, a3));
#pragma unroll
            for (int o = 16; o; o >>= 1) m = fmaxf(m, __shfl_xor_sync(0xffffffffu, m, o));
            a0 = expf(a0 - m); a1 = expf(a1 - m); a2 = expf(a2 - m); a3 = expf(a3 - m);
            float ssum = a0 + a1 + a2 + a3;
#pragma unroll
            for (int o = 16; o; o >>= 1) ssum += __shfl_xor_sync(0xffffffffu, ssum, o);
            float inv = 1.0f / ssum;
            float4 wv;
            wv.x = a0 * inv; wv.y = a1 * inv; wv.z = a2 * inv; wv.w = a3 * inv;
            *(float4*)&attn_s[w * 132 + n0 + 4 * (l >= 16)] = wv;
        }
        __syncthreads();

        // ---- B: ctx[d] = sum_n attn[h(d)][n] * v[n][d]  (packed FFMA2) ----
        {
            int d = tid >> 1, nh = tid & 1, hh = d >> 5;
            const ulonglong2* ap2 = (const ulonglong2*)(attn_s + hh * 132 + nh * 68);
            u64 acc2 = 0ULL;
#pragma unroll
            for (int i = 0; i < 16; i++) {
                ulonglong2 av = ap2[i];
                ffma2(acc2, av.x, v2[2 * i]);
                ffma2(acc2, av.y, v2[2 * i + 1]);
            }
            float2 ac = unpack2(acc2);
            float acc = ac.x + ac.y;
            acc += __shfl_xor_sync(0xffffffffu, acc, 1);
            if (!nh) ctx_s[d] = acc;
        }
        __syncthreads();

        // ---- C: logits partials (packed FFMA2; first MRC float4 from regs) ----
        {
            const ulonglong2* c2 = (const ulonglong2*)ctx_s + pL * 16;
            const ulonglong2* mr = (const ulonglong2*)Ms4T + (pL * 16) * MTU + nL;
            u64 sA = 0ULL, sB = 0ULL;
#pragma unroll
            for (int i = 0; i < MRC; i++) {
                ulonglong2 c = c2[i];
                ffma2(sA, Mreg2[2 * i], c.x);
                ffma2(sB, Mreg2[2 * i + 1], c.y);
            }
#pragma unroll
            for (int i = MRC; i < 16; i++) {
                ulonglong2 mv = mr[i * MTU];
                ulonglong2 c = c2[i];
                ffma2(sA, mv.x, c.x);
                ffma2(sB, mv.y, c.y);
            }
            float2 a = unpack2(sA), bq = unpack2(sB);
            lp_part[nL][pL] = (a.x + a.y) + (bq.x + bq.y);
        }
        __syncthreads();

        // ---- E: warps 0-8: raw logits (one LDS.128 per j), packed-key argmax,
        //         state update, issue next P load; warp 8 tanh+lse behind it. ----
        if (w <= 8) {
            float r[4];
            float bv = -3.0e38f; int bi = 0;
#pragma unroll
            for (int j = 0; j < 4; j++) {
                int n = l + 32 * j;
                float4 q = *(const float4*)lp_part[n];
                float s = ((q.x + q.y) + q.z) + q.w;   // same order as p0+p1+p2+p3
                float rr = fmaf(SCALE_, s, bd_r[j]);
                if ((visD >> j) & 1u) rr = NEGV;
                r[j] = rr;
                if (rr > bv) { bv = rr; bi = n; }
            }
            // packed key: order-preserving float map in high 32, (127-n) low.
            unsigned ub = __float_as_uint(bv);
            ub ^= (ub & 0x80000000u) ? 0xFFFFFFFFu : 0x80000000u;
            u64 key = ((u64)ub << 32) | (unsigned)(127 - bi);
#pragma unroll
            for (int o = 16; o; o >>= 1) {
                u64 ok = __shfl_xor_sync(0xffffffffu, key, o);
                if (ok > key) key = ok;
            }
            int bw = 127 - (int)(key & 0xFFu);
            // state update + immediately issue next P row load
            if ((bw >> 2) == l) visA |= 1u << (bw & 3);
            if ((bw & 31) == l) visD |= 1u << (bw >> 5);
            if (w < 8) pv = Pb[(size_t)bw * 256 + w * 32 + l];

            // warp 8: tanh only here (off the critical path), then lse + logp
            if (w == 8) {
                unsigned uu = (unsigned)(key >> 32);
                unsigned bits = (uu & 0x80000000u) ? (uu ^ 0x80000000u) : ~uu;
                float bvg = __uint_as_float(bits);     // winning raw logit
                float bvt = tanhf(bvg) * CLIPV;
                float es = 0.f;
#pragma unroll
                for (int j = 0; j < 4; j++) {
                    float lvt = (r[j] == NEGV) ? NEGV : tanhf(r[j]) * CLIPV;
                    es += expf(lvt - bvt);
                }
#pragma unroll
                for (int o = 16; o; o >>= 1) es += __shfl_xor_sync(0xffffffffu, es, o);
                lp -= logf(es);
            }
        }
        // no trailing barrier: bar1..bar3 of the next step order all smem reuse
    }

    if (tid == 256) out[b] = lp;   // warp 8, lane 0
}

// ---------------- host launch ----------------
extern "C" void kernel_launch(void* const* d_in, const int* in_sizes, int n_in,
                              void* d_out, int out_size) {
    const float* ne    = (const float*)d_in[0];
    const float* Wqkv  = (const float*)d_in[1];
    const float* bqkv  = (const float*)d_in[2];
    const float* Wfix  = (const float*)d_in[3];
    const float* bfix  = (const float*)d_in[4];
    const float* Wstep = (const float*)d_in[5];
    const float* bstep = (const float*)d_in[6];
    const float* Wmlp  = (const float*)d_in[7];
    const float* bmlp  = (const float*)d_in[8];
    float* out = (float*)d_out;

    float *p_qkv = nullptr, *p_Qc = nullptr, *p_M = nullptr, *p_P = nullptr, *p_wt = nullptr;
    cudaGetSymbolAddress((void**)&p_qkv, g_qkv);
    cudaGetSymbolAddress((void**)&p_Qc, g_Qc);
    cudaGetSymbolAddress((void**)&p_M, g_M);
    cudaGetSymbolAddress((void**)&p_P, g_P);
    cudaGetSymbolAddress((void**)&p_wt, g_wt);

    size_t dec_smem = (size_t)64 * MTU * sizeof(float4);   // 132096
    cudaFuncSetAttribute(decode_k, cudaFuncAttributeMaxDynamicSharedMemorySize,
                         (int)dec_smem);
    size_t gemm_smem = 4 * 4096 * sizeof(float);           // 65536
    cudaFuncSetAttribute(sgemm_k, cudaFuncAttributeMaxDynamicSharedMemorySize,
                         (int)gemm_smem);

    mean_k<<<B_, E_>>>(ne);
    qfirst_k<<<B_, E_>>>(ne, Wfix, bfix, Wstep, bstep);
    wtrans_k<<<64, 256>>>(Wmlp);

    sgemm_k<<<dim3(768 / 128, (B_ * N_) / 128), 256, gemm_smem>>>(
        ne, Wqkv, bqkv, p_qkv, E_, E_, 768, 768);
    sgemm_k<<<dim3(E_ / 128, (B_ * N_) / 128), 256, gemm_smem>>>(
        ne, Wstep + 256 * 256, nullptr, p_Qc, E_, E_, E_, E_);
    sgemm_k<<<dim3(E_ / 128, (B_ * N_) / 128), 256, gemm_smem>>>(
        p_qkv + 512, p_wt, nullptr, p_M, E_, 768, E_, E_);
    pmat_k<<<B_ * H_, 256>>>(p_P);
    vtrans_k<<<B_ * 8, 256>>>();
    bdot_k<<<(B_ * N_) / 8, 256>>>(bmlp);

    decode_k<<<B_, 512, dec_smem>>>(out);
}